// round 15
// baseline (speedup 1.0000x reference)
#include <cuda_runtime.h>
#include <cuda_bf16.h>
#include <cstdint>

#define Bb     2
#define LL     2048
#define DM     512
#define ED_    1024
#define NS     16
#define DTR    32
#define DFF    1024
#define BLr    (Bb*LL)            /* 4096 rows */
#define NCHUNK 16
#define CLEN   (LL/NCHUNK)        /* 128 */
#define NCHAIN 2048
#define KSPL   8

typedef unsigned long long ull;

/* ------------------------------------------------------------------ */
__device__ float g_xz   [2*BLr*2*ED_];
__device__ float g_xc   [2*BLr*ED_];
__device__ float g_dbl  [2*BLr*64];
__device__ float g_part [2*KSPL*BLr*64];
__device__ float g_delta[2*BLr*ED_];
__device__ float g_U    [2*BLr*DM];
__device__ float g_V2   [2*BLr*DM];
__device__ float g_hloc [2*NCHUNK*NCHAIN*NS];
__device__ float g_aprod[2*NCHUNK*NCHAIN*NS];
__device__ float g_hin  [2*NCHUNK*NCHAIN*NS];
__device__ __nv_bfloat16 g_Ahi[12*1024*1024];
__device__ __nv_bfloat16 g_Alo[12*1024*1024];
__device__ __nv_bfloat16 g_Bhi[2*1024*1024];
__device__ __nv_bfloat16 g_Blo[2*1024*1024];

/* ------------------------------------------------------------------ */
__device__ __forceinline__ float softplusf(float x) {
    return fmaxf(x, 0.f) + log1pf(expf(-fabsf(x)));
}
__device__ __forceinline__ float siluf(float x) {
    return x / (1.f + __expf(-x));
}
__device__ __forceinline__ uint32_t smem_u32(const void* p) {
    uint32_t a;
    asm("{ .reg .u64 t; cvta.to.shared.u64 t, %1; cvt.u32.u64 %0, t; }"
        : "=r"(a) : "l"(p));
    return a;
}
__device__ __forceinline__ void cp16(uint32_t dst, const void* src) {
    asm volatile("cp.async.ca.shared.global [%0], [%1], 16;"
                 :: "r"(dst), "l"(src));
}
__device__ __forceinline__ void cp_commit() {
    asm volatile("cp.async.commit_group;");
}
__device__ __forceinline__ void cp_wait0() {
    asm volatile("cp.async.wait_group 0;" ::: "memory");
}

/* ================= HMMA helpers =================================== */
__device__ __forceinline__ void ldm_x4(uint32_t* r, uint32_t addr) {
    asm volatile("ldmatrix.sync.aligned.m8n8.x4.shared.b16 {%0,%1,%2,%3}, [%4];"
                 : "=r"(r[0]), "=r"(r[1]), "=r"(r[2]), "=r"(r[3]) : "r"(addr));
}
__device__ __forceinline__ void ldm_x4t(uint32_t* r, uint32_t addr) {
    asm volatile("ldmatrix.sync.aligned.m8n8.x4.trans.shared.b16 {%0,%1,%2,%3}, [%4];"
                 : "=r"(r[0]), "=r"(r[1]), "=r"(r[2]), "=r"(r[3]) : "r"(addr));
}
__device__ __forceinline__ void mma_bf16(float* c, const uint32_t* a,
                                         const uint32_t* b) {
    asm volatile(
        "mma.sync.aligned.m16n8k16.row.col.f32.bf16.bf16.f32 "
        "{%0,%1,%2,%3},{%4,%5,%6,%7},{%8,%9},{%0,%1,%2,%3};"
        : "+f"(c[0]), "+f"(c[1]), "+f"(c[2]), "+f"(c[3])
        : "r"(a[0]), "r"(a[1]), "r"(a[2]), "r"(a[3]), "r"(b[0]), "r"(b[1]));
}

/* ================= fp32 -> bf16 hi/lo convert ===================== */
__global__ void cvt_kernel(const float* __restrict__ s,
                           __nv_bfloat16* __restrict__ hi,
                           __nv_bfloat16* __restrict__ lo, int n4)
{
    int i = blockIdx.x * 256 + threadIdx.x;
    if (i >= n4) return;
    float4 v = ((const float4*)s)[i];
    __nv_bfloat162 h01 = __floats2bfloat162_rn(v.x, v.y);
    float2 f01 = __bfloat1622float2(h01);
    __nv_bfloat162 l01 = __floats2bfloat162_rn(v.x - f01.x, v.y - f01.y);
    __nv_bfloat162 h23 = __floats2bfloat162_rn(v.z, v.w);
    float2 f23 = __bfloat1622float2(h23);
    __nv_bfloat162 l23 = __floats2bfloat162_rn(v.z - f23.x, v.w - f23.y);
    ((__nv_bfloat162*)hi)[i * 2]     = h01;
    ((__nv_bfloat162*)hi)[i * 2 + 1] = h23;
    ((__nv_bfloat162*)lo)[i * 2]     = l01;
    ((__nv_bfloat162*)lo)[i * 2 + 1] = l23;
}

__global__ void cvt2_kernel(const float* __restrict__ s0,
                            const float* __restrict__ s1,
                            __nv_bfloat16* __restrict__ hi,
                            __nv_bfloat16* __restrict__ lo,
                            size_t stride, int n4)
{
    int i = blockIdx.x * 256 + threadIdx.x;
    if (i >= n4) return;
    const float* s = blockIdx.z ? s1 : s0;
    hi += blockIdx.z * stride;
    lo += blockIdx.z * stride;
    float4 v = ((const float4*)s)[i];
    __nv_bfloat162 h01 = __floats2bfloat162_rn(v.x, v.y);
    float2 f01 = __bfloat1622float2(h01);
    __nv_bfloat162 l01 = __floats2bfloat162_rn(v.x - f01.x, v.y - f01.y);
    __nv_bfloat162 h23 = __floats2bfloat162_rn(v.z, v.w);
    float2 f23 = __bfloat1622float2(h23);
    __nv_bfloat162 l23 = __floats2bfloat162_rn(v.z - f23.x, v.w - f23.y);
    ((__nv_bfloat162*)hi)[i * 2]     = h01;
    ((__nv_bfloat162*)hi)[i * 2 + 1] = h23;
    ((__nv_bfloat162*)lo)[i * 2]     = l01;
    ((__nv_bfloat162*)lo)[i * 2 + 1] = l23;
}

/* z0: straight x cvt; z1: L-flipped x cvt */
__global__ void cvt_x2_kernel(const float* __restrict__ s,
                              __nv_bfloat16* __restrict__ hi,
                              __nv_bfloat16* __restrict__ lo, size_t stride)
{
    int i = blockIdx.x * 256 + threadIdx.x;
    hi += blockIdx.z * stride;
    lo += blockIdx.z * stride;
    float4 v;
    if (blockIdx.z == 0) {
        v = ((const float4*)s)[i];
    } else {
        int c = i & 127;
        int r = i >> 7;
        int b = r >> 11;
        int l = r & 2047;
        v = ((const float4*)s)[(size_t)(((b << 11) + (2047 - l)) << 7) + c];
    }
    __nv_bfloat162 h01 = __floats2bfloat162_rn(v.x, v.y);
    float2 f01 = __bfloat1622float2(h01);
    __nv_bfloat162 l01 = __floats2bfloat162_rn(v.x - f01.x, v.y - f01.y);
    __nv_bfloat162 h23 = __floats2bfloat162_rn(v.z, v.w);
    float2 f23 = __bfloat1622float2(h23);
    __nv_bfloat162 l23 = __floats2bfloat162_rn(v.z - f23.x, v.w - f23.y);
    ((__nv_bfloat162*)hi)[i * 2]     = h01;
    ((__nv_bfloat162*)hi)[i * 2 + 1] = h23;
    ((__nv_bfloat162*)lo)[i * 2]     = l01;
    ((__nv_bfloat162*)lo)[i * 2 + 1] = l23;
}

/* compact dt columns of dbl (stride 64 -> 32) into bf16 hi/lo */
__global__ void cvt_dt_kernel(const float* __restrict__ dbl,
                              __nv_bfloat16* __restrict__ hi,
                              __nv_bfloat16* __restrict__ lo)
{
    int i = blockIdx.x * 256 + threadIdx.x;     /* < 2*4096*8 */
    int r  = i >> 3;
    int c4 = (i & 7) * 4;
    float4 v = *(const float4*)&dbl[(size_t)r * 64 + c4];
    __nv_bfloat162 h01 = __floats2bfloat162_rn(v.x, v.y);
    float2 f01 = __bfloat1622float2(h01);
    __nv_bfloat162 l01 = __floats2bfloat162_rn(v.x - f01.x, v.y - f01.y);
    __nv_bfloat162 h23 = __floats2bfloat162_rn(v.z, v.w);
    float2 f23 = __bfloat1622float2(h23);
    __nv_bfloat162 l23 = __floats2bfloat162_rn(v.z - f23.x, v.w - f23.y);
    size_t d = (size_t)r * 32 + c4;
    *(__nv_bfloat162*)(hi + d)     = h01;
    *(__nv_bfloat162*)(hi + d + 2) = h23;
    *(__nv_bfloat162*)(lo + d)     = l01;
    *(__nv_bfloat162*)(lo + d + 2) = l23;
}

/* ======== split-bf16 HMMA GEMM, 2-stage cp.async, occ 2 =========== */
/* ep: 0 none, 1 bias+relu, 2 bias, 3 softplus(bias+x)                */
#define OFF_ALO 10240
#define OFF_BHI 20480
#define OFF_BLO 29184
#define MBUF    37888
#define MM_SMEM (2*MBUF)

__global__ void __launch_bounds__(256, 2)
mma_gemm(const __nv_bfloat16* __restrict__ Ah,
         const __nv_bfloat16* __restrict__ Al, size_t sA,
         const __nv_bfloat16* __restrict__ Bh,
         const __nv_bfloat16* __restrict__ Bl, size_t sB,
         int N, int K,
         float* __restrict__ C, size_t sC,
         __nv_bfloat16* __restrict__ Chi, __nv_bfloat16* __restrict__ Clo,
         const float* __restrict__ bias0, const float* __restrict__ bias1,
         int ep)
{
    extern __shared__ char smc[];
    const int z = blockIdx.z;
    const float* bias = z ? bias1 : bias0;
    Ah += (size_t)z * sA;  Al += (size_t)z * sA;
    Bh += (size_t)z * sB;  Bl += (size_t)z * sB;
    if (C)   C   += (size_t)z * sC;
    if (Chi) { Chi += (size_t)z * sC; Clo += (size_t)z * sC; }

    const int tid  = threadIdx.x;
    const int lane = tid & 31;
    const int wid  = tid >> 5;
    const int wm   = wid & 1;
    const int wn   = wid >> 1;
    const int m0 = blockIdx.y * 128;
    const int n0 = blockIdx.x * 128;

    const int a_row = tid >> 2;
    const int a_ch  = tid & 3;
    const int b_row = tid >> 4;
    const int b_ch  = tid & 15;

    const __nv_bfloat16* gA0h = Ah + (size_t)(m0 + a_row) * K + a_ch * 8;
    const __nv_bfloat16* gA1h = gA0h + (size_t)64 * K;
    const __nv_bfloat16* gA0l = Al + (size_t)(m0 + a_row) * K + a_ch * 8;
    const __nv_bfloat16* gA1l = gA0l + (size_t)64 * K;
    const __nv_bfloat16* gB0h = Bh + (size_t)b_row * N + n0 + b_ch * 8;
    const __nv_bfloat16* gB1h = gB0h + (size_t)16 * N;
    const __nv_bfloat16* gB0l = Bl + (size_t)b_row * N + n0 + b_ch * 8;
    const __nv_bfloat16* gB1l = gB0l + (size_t)16 * N;

    const uint32_t sbase = smem_u32(smc);
    const uint32_t sa0 = (uint32_t)(a_row * 80 + a_ch * 16);
    const uint32_t sa1 = (uint32_t)((a_row + 64) * 80 + a_ch * 16);
    const uint32_t sb0 = (uint32_t)(b_row * 272 + b_ch * 16);
    const uint32_t sb1 = (uint32_t)((b_row + 16) * 272 + b_ch * 16);

    float acc[4][4][4];
#pragma unroll
    for (int i = 0; i < 4; ++i)
#pragma unroll
        for (int j = 0; j < 4; ++j)
#pragma unroll
            for (int q = 0; q < 4; ++q) acc[i][j][q] = 0.f;

    /* prolog: tile 0 via cp.async */
    {
        const uint32_t d = sbase;
        cp16(d + sa0, gA0h);            cp16(d + sa1, gA1h);
        cp16(d + OFF_ALO + sa0, gA0l);  cp16(d + OFF_ALO + sa1, gA1l);
        cp16(d + OFF_BHI + sb0, gB0h);  cp16(d + OFF_BHI + sb1, gB1h);
        cp16(d + OFF_BLO + sb0, gB0l);  cp16(d + OFF_BLO + sb1, gB1l);
        cp_commit();
        cp_wait0();
    }
    __syncthreads();

    const int NIT = K >> 5;
    for (int it = 0; it < NIT; ++it) {
        if (it + 1 < NIT) {
            const int kq = (it + 1) << 5;
            const size_t bo = (size_t)kq * N;
            const uint32_t d = sbase + (uint32_t)(((it + 1) & 1) * MBUF);
            cp16(d + sa0, gA0h + kq);            cp16(d + sa1, gA1h + kq);
            cp16(d + OFF_ALO + sa0, gA0l + kq);  cp16(d + OFF_ALO + sa1, gA1l + kq);
            cp16(d + OFF_BHI + sb0, gB0h + bo);  cp16(d + OFF_BHI + sb1, gB1h + bo);
            cp16(d + OFF_BLO + sb0, gB0l + bo);  cp16(d + OFF_BLO + sb1, gB1l + bo);
            cp_commit();
        }

        const uint32_t base = sbase + (uint32_t)((it & 1) * MBUF);
#pragma unroll
        for (int ks = 0; ks < 2; ++ks) {
            uint32_t ah[4][4], al[4][4], bh[2][4], bl[2][4];
            uint32_t aaddr = base + (uint32_t)((wm * 64 + (lane & 15)) * 80
                               + ks * 32 + ((lane >> 4) & 1) * 16);
#pragma unroll
            for (int mf = 0; mf < 4; ++mf) {
                ldm_x4(ah[mf], aaddr + mf * 1280);
                ldm_x4(al[mf], aaddr + OFF_ALO + mf * 1280);
            }
            uint32_t baddr = base + OFF_BHI
                + (uint32_t)((ks * 16 + (lane & 15)) * 272
                + (wn * 32 + ((lane >> 4) & 1) * 8) * 2);
#pragma unroll
            for (int np = 0; np < 2; ++np) {
                ldm_x4t(bh[np], baddr + np * 32);
                ldm_x4t(bl[np], baddr + (OFF_BLO - OFF_BHI) + np * 32);
            }
#pragma unroll
            for (int mf = 0; mf < 4; ++mf)
#pragma unroll
                for (int nf = 0; nf < 4; ++nf) {
                    const uint32_t* bhp = &bh[nf >> 1][(nf & 1) * 2];
                    const uint32_t* blp = &bl[nf >> 1][(nf & 1) * 2];
                    mma_bf16(acc[mf][nf], ah[mf], bhp);
                    mma_bf16(acc[mf][nf], ah[mf], blp);
                    mma_bf16(acc[mf][nf], al[mf], bhp);
                }
        }

        if (it + 1 < NIT) cp_wait0();
        __syncthreads();
    }

    /* ---- epilogue ---- */
    const int row = m0 + wm * 64 + (lane >> 2);
    const int col = n0 + wn * 32 + (lane & 3) * 2;
#pragma unroll
    for (int nf = 0; nf < 4; ++nf) {
        const int c = col + nf * 8;
        float2 bv = make_float2(0.f, 0.f);
        if (ep) bv = *(const float2*)(bias + c);
#pragma unroll
        for (int mf = 0; mf < 4; ++mf) {
            const int r = row + mf * 16;
            float2 v0 = make_float2(acc[mf][nf][0] + bv.x, acc[mf][nf][1] + bv.y);
            float2 v1 = make_float2(acc[mf][nf][2] + bv.x, acc[mf][nf][3] + bv.y);
            if (ep == 1) {
                v0.x = fmaxf(v0.x, 0.f); v0.y = fmaxf(v0.y, 0.f);
                v1.x = fmaxf(v1.x, 0.f); v1.y = fmaxf(v1.y, 0.f);
            } else if (ep == 3) {
                v0.x = softplusf(v0.x);  v0.y = softplusf(v0.y);
                v1.x = softplusf(v1.x);  v1.y = softplusf(v1.y);
            }
            if (C) {
                *(float2*)(C + (size_t)r * N + c)       = v0;
                *(float2*)(C + (size_t)(r + 8) * N + c) = v1;
            }
            if (Chi) {
                __nv_bfloat162 h0 = __floats2bfloat162_rn(v0.x, v0.y);
                float2 f0 = __bfloat1622float2(h0);
                __nv_bfloat162 l0 = __floats2bfloat162_rn(v0.x - f0.x, v0.y - f0.y);
                __nv_bfloat162 h1 = __floats2bfloat162_rn(v1.x, v1.y);
                float2 f1 = __bfloat1622float2(h1);
                __nv_bfloat162 l1 = __floats2bfloat162_rn(v1.x - f1.x, v1.y - f1.y);
                *(__nv_bfloat162*)(Chi + (size_t)r * N + c)       = h0;
                *(__nv_bfloat162*)(Chi + (size_t)(r + 8) * N + c) = h1;
                *(__nv_bfloat162*)(Clo + (size_t)r * N + c)       = l0;
                *(__nv_bfloat162*)(Clo + (size_t)(r + 8) * N + c) = l1;
            }
        }
    }
}

/* ================= xproj split-K ==================================== */
__global__ __launch_bounds__(256)
void xproj_kernel(const float* __restrict__ xc,
                  const float* __restrict__ B0, const float* __restrict__ B1,
                  float* __restrict__ part)
{
    __shared__ float As[16][68];
    __shared__ float Bs[16][68];

    const int ks  = blockIdx.x;
    const int dir = blockIdx.z;
    const float* A = xc + (size_t)dir * BLr * ED_;
    const float* B = dir ? B1 : B0;
    float* P = part + ((size_t)dir * KSPL + ks) * BLr * 64;

    const int tid  = threadIdx.x;
    const int tx   = tid & 15;
    const int ty   = tid >> 4;
    const int row0 = blockIdx.y * 64;
    const int kbase = ks * (ED_ / KSPL);

    const int ar = tid >> 2;
    const int ak = (tid & 3) << 2;
    const int bk = tid >> 4;
    const int bn = (tid & 15) << 2;

    float acc[4][4];
#pragma unroll
    for (int i = 0; i < 4; ++i)
#pragma unroll
        for (int j = 0; j < 4; ++j) acc[i][j] = 0.f;

    for (int k0 = kbase; k0 < kbase + ED_ / KSPL; k0 += 16) {
        float4 avv = *(const float4*)(A + (size_t)(row0 + ar) * ED_ + k0 + ak);
        As[ak + 0][ar] = avv.x;
        As[ak + 1][ar] = avv.y;
        As[ak + 2][ar] = avv.z;
        As[ak + 3][ar] = avv.w;
        *(float4*)&Bs[bk][bn] =
            *(const float4*)(B + (size_t)(k0 + bk) * 64 + bn);
        __syncthreads();

#pragma unroll
        for (int kk = 0; kk < 16; ++kk) {
            float4 a = *(const float4*)&As[kk][ty << 2];
            float4 b = *(const float4*)&Bs[kk][tx << 2];
            float ai[4] = {a.x, a.y, a.z, a.w};
            float bj[4] = {b.x, b.y, b.z, b.w};
#pragma unroll
            for (int i = 0; i < 4; ++i)
#pragma unroll
                for (int j = 0; j < 4; ++j)
                    acc[i][j] = fmaf(ai[i], bj[j], acc[i][j]);
        }
        __syncthreads();
    }

    const int m0 = row0 + (ty << 2);
    const int n0 = tx << 2;
#pragma unroll
    for (int i = 0; i < 4; ++i)
        *(float4*)(P + (size_t)(m0 + i) * 64 + n0) =
            make_float4(acc[i][0], acc[i][1], acc[i][2], acc[i][3]);
}

__global__ void xproj_reduce(const float* __restrict__ part,
                             float* __restrict__ dbl)
{
    const int idx = blockIdx.x * 256 + threadIdx.x;
    const int dir = idx >> 16;
    const int r   = idx & 65535;
    const float4* p = (const float4*)part + (size_t)dir * KSPL * 65536 + r;
    float4 s = make_float4(0.f, 0.f, 0.f, 0.f);
#pragma unroll
    for (int ks = 0; ks < KSPL; ++ks) {
        float4 v = p[(size_t)ks * 65536];
        s.x += v.x; s.y += v.y; s.z += v.z; s.w += v.w;
    }
    ((float4*)dbl)[idx] = s;
}

/* ------------------------------------------------------------------ */
__global__ void conv_silu_kernel(const float* __restrict__ xz,
                                 const float* __restrict__ cw0,
                                 const float* __restrict__ cb0,
                                 const float* __restrict__ cw1,
                                 const float* __restrict__ cb1,
                                 float* __restrict__ xc)
{
    const int dir = blockIdx.z;
    const float* cw = dir ? cw1 : cw0;
    const float* cb = dir ? cb1 : cb0;
    xz += (size_t)dir * BLr * 2 * ED_;
    xc += (size_t)dir * BLr * ED_;

    int idx = blockIdx.x * 256 + threadIdx.x;
    int e = idx & 1023;
    int r = idx >> 10;
    int l = r & 2047;
    int b = r >> 11;
    float s = cb[e];
#pragma unroll
    for (int k = 0; k < 4; ++k) {
        int ll = l + k - 3;
        if (ll >= 0)
            s = fmaf(xz[((size_t)((b << 11) + ll) << 11) + e], cw[(e << 2) + k], s);
    }
    xc[idx] = siluf(s);
}

/* ================= chunked selective scan (4 states/lane) ========== */
__global__ __launch_bounds__(256)
void scanA_kernel(const float* __restrict__ delta,
                  const float* __restrict__ xc,
                  const float* __restrict__ dbl,
                  const float* __restrict__ Alog0,
                  const float* __restrict__ Alog1,
                  float* __restrict__ hloc, float* __restrict__ aprod)
{
    const int dir  = blockIdx.y;
    const int warp = blockIdx.x * 8 + (threadIdx.x >> 5);
    const int lane = threadIdx.x & 31;
    const int c    = lane >> 2;
    const int g    = lane & 3;
    const int chunk = warp >> 8;
    const int cg    = warp & 255;
    const int chain = cg * 8 + c;
    const int b = chain >> 10;
    const int e = chain & 1023;

    const float* Alog = dir ? Alog1 : Alog0;
    delta += (size_t)dir * BLr * ED_;
    xc    += (size_t)dir * BLr * ED_;
    dbl   += (size_t)dir * BLr * 64;

    float4 alv = *(const float4*)&Alog[(e << 4) + g * 4];
    const float a0 = -expf(alv.x), a1 = -expf(alv.y),
                a2 = -expf(alv.z), a3 = -expf(alv.w);
    float h0 = 0.f, h1 = 0.f, h2 = 0.f, h3 = 0.f;
    float p0 = 1.f, p1 = 1.f, p2 = 1.f, p3 = 1.f;
    const int r0 = (b << 11) + chunk * CLEN;

    for (int l = 0; l < CLEN; l += 4) {
        float d[4], xv[4];
        float4 bv[4];
#pragma unroll
        for (int s = 0; s < 4; ++s) {
            int row = r0 + l + s;
            d[s]  = __ldg(&delta[((size_t)row << 10) + e]);
            xv[s] = __ldg(&xc   [((size_t)row << 10) + e]);
            bv[s] = *(const float4*)&dbl[(row << 6) + 32 + g * 4];
        }
#pragma unroll
        for (int s = 0; s < 4; ++s) {
            const float t = d[s] * xv[s];
            float dA;
            dA = __expf(d[s] * a0); h0 = fmaf(dA, h0, t * bv[s].x); p0 *= dA;
            dA = __expf(d[s] * a1); h1 = fmaf(dA, h1, t * bv[s].y); p1 *= dA;
            dA = __expf(d[s] * a2); h2 = fmaf(dA, h2, t * bv[s].z); p2 *= dA;
            dA = __expf(d[s] * a3); h3 = fmaf(dA, h3, t * bv[s].w); p3 *= dA;
        }
    }
    size_t idx = ((size_t)dir * NCHUNK + chunk) * (NCHAIN * NS)
               + (size_t)chain * NS + g * 4;
    *(float4*)&hloc[idx]  = make_float4(h0, h1, h2, h3);
    *(float4*)&aprod[idx] = make_float4(p0, p1, p2, p3);
}

__global__ void scanB_kernel(const float* __restrict__ hloc,
                             const float* __restrict__ aprod,
                             float* __restrict__ hin)
{
    const int dir = blockIdx.y;
    const int t = blockIdx.x * 256 + threadIdx.x;
    const size_t base = (size_t)dir * NCHUNK * NCHAIN * NS;
    float h = 0.f;
#pragma unroll
    for (int c = 0; c < NCHUNK; ++c) {
        size_t idx = base + (size_t)c * NCHAIN * NS + t;
        hin[idx] = h;
        h = fmaf(aprod[idx], h, hloc[idx]);
    }
}

__global__ __launch_bounds__(256)
void scanC_kernel(const float* __restrict__ delta,
                  const float* __restrict__ xc,
                  const float* __restrict__ dbl,
                  const float* __restrict__ xz,
                  const float* __restrict__ Alog0,
                  const float* __restrict__ Alog1,
                  const float* __restrict__ Dp0,
                  const float* __restrict__ Dp1,
                  const float* __restrict__ hin,
                  __nv_bfloat16* __restrict__ yhi,
                  __nv_bfloat16* __restrict__ ylo)
{
    const int dir  = blockIdx.y;
    const int warp = blockIdx.x * 8 + (threadIdx.x >> 5);
    const int lane = threadIdx.x & 31;
    const int c    = lane >> 2;
    const int g    = lane & 3;
    const int chunk = warp >> 8;
    const int cg    = warp & 255;
    const int chain = cg * 8 + c;
    const int b = chain >> 10;
    const int e = chain & 1023;

    const float* Alog = dir ? Alog1 : Alog0;
    const float* Dp   = dir ? Dp1   : Dp0;
    delta += (size_t)dir * BLr * ED_;
    xc    += (size_t)dir * BLr * ED_;
    yhi   += (size_t)dir * BLr * ED_;
    ylo   += (size_t)dir * BLr * ED_;
    dbl   += (size_t)dir * BLr * 64;
    xz    += (size_t)dir * BLr * 2 * ED_;

    float4 alv = *(const float4*)&Alog[(e << 4) + g * 4];
    const float a0 = -expf(alv.x), a1 = -expf(alv.y),
                a2 = -expf(alv.z), a3 = -expf(alv.w);
    const float dc = Dp[e];
    float4 hv = *(const float4*)&hin[((size_t)dir * NCHUNK + chunk)
               * (NCHAIN * NS) + (size_t)chain * NS + g * 4];
    float h0 = hv.x, h1 = hv.y, h2 = hv.z, h3 = hv.w;
    const int r0 = (b << 11) + chunk * CLEN;

    for (int l = 0; l < CLEN; l += 4) {
        float d[4], xv[4];
        float4 bv[4], cv[4];
#pragma unroll
        for (int s = 0; s < 4; ++s) {
            int row = r0 + l + s;
            d[s]  = __ldg(&delta[((size_t)row << 10) + e]);
            xv[s] = __ldg(&xc   [((size_t)row << 10) + e]);
            bv[s] = *(const float4*)&dbl[(row << 6) + 32 + g * 4];
            cv[s] = *(const float4*)&dbl[(row << 6) + 48 + g * 4];
        }
        float p[4];
#pragma unroll
        for (int s = 0; s < 4; ++s) {
            const float t = d[s] * xv[s];
            float dA;
            dA = __expf(d[s] * a0); h0 = fmaf(dA, h0, t * bv[s].x);
            dA = __expf(d[s] * a1); h1 = fmaf(dA, h1, t * bv[s].y);
            dA = __expf(d[s] * a2); h2 = fmaf(dA, h2, t * bv[s].z);
            dA = __expf(d[s] * a3); h3 = fmaf(dA, h3, t * bv[s].w);
            p[s] = h0 * cv[s].x + h1 * cv[s].y + h2 * cv[s].z + h3 * cv[s].w;
        }
#pragma unroll
        for (int s = 0; s < 4; ++s) {
            p[s] += __shfl_xor_sync(0xffffffffu, p[s], 1);
            p[s] += __shfl_xor_sync(0xffffffffu, p[s], 2);
        }
        if (g == 0) {
#pragma unroll
            for (int s = 0; s < 4; ++s) {
                int row = r0 + l + s;
                float zv = xz[((size_t)row << 11) + 1024 + e];
                float val = (p[s] + xv[s] * dc) * siluf(zv);
                __nv_bfloat16 hb = __float2bfloat16_rn(val);
                yhi[((size_t)row << 10) + e] = hb;
                ylo[((size_t)row << 10) + e] =
                    __float2bfloat16_rn(val - __bfloat162float(hb));
            }
        }
    }
}

/* ---- layernorm; also emits bf16 hi/lo of the result -------------- */
__global__ __launch_bounds__(128)
void ln_kernel(float* __restrict__ U, const float* __restrict__ g,
               const float* __restrict__ bb,
               __nv_bfloat16* __restrict__ hi, __nv_bfloat16* __restrict__ lo)
{
    int row = blockIdx.x;
    float4* p = (float4*)(U + (size_t)row * DM);
    int tid = threadIdx.x;
    int lane = tid & 31, w = tid >> 5;
    __shared__ float red[4];

    float4 v = p[tid];
    float s = v.x + v.y + v.z + v.w;
#pragma unroll
    for (int o = 16; o; o >>= 1) s += __shfl_xor_sync(0xffffffffu, s, o);
    if (!lane) red[w] = s;
    __syncthreads();
    float mu = (red[0] + red[1] + red[2] + red[3]) * (1.f / 512.f);

    float dx = v.x - mu, dy = v.y - mu, dz = v.z - mu, dw = v.w - mu;
    float s2 = dx*dx + dy*dy + dz*dz + dw*dw;
#pragma unroll
    for (int o = 16; o; o >>= 1) s2 += __shfl_xor_sync(0xffffffffu, s2, o);
    __syncthreads();
    if (!lane) red[w] = s2;
    __syncthreads();
    float var  = (red[0] + red[1] + red[2] + red[3]) * (1.f / 512.f);
    float rstd = rsqrtf(var + 1e-5f);

    int c = tid << 2;
    float4 go = *(const float4*)(g + c);
    float4 bo = *(const float4*)(bb + c);
    float4 o;
    o.x = dx * rstd * go.x + bo.x;
    o.y = dy * rstd * go.y + bo.y;
    o.z = dz * rstd * go.z + bo.z;
    o.w = dw * rstd * go.w + bo.w;
    p[tid] = o;

    __nv_bfloat162 h01 = __floats2bfloat162_rn(o.x, o.y);
    float2 f01 = __bfloat1622float2(h01);
    __nv_bfloat162 l01 = __floats2bfloat162_rn(o.x - f01.x, o.y - f01.y);
    __nv_bfloat162 h23 = __floats2bfloat162_rn(o.z, o.w);
    float2 f23 = __bfloat1622float2(h23);
    __nv_bfloat162 l23 = __floats2bfloat162_rn(o.z - f23.x, o.w - f23.y);
    size_t base = (size_t)row * DM + c;
    *(__nv_bfloat162*)(hi + base)     = h01;
    *(__nv_bfloat162*)(hi + base + 2) = h23;
    *(__nv_bfloat162*)(lo + base)     = l01;
    *(__nv_bfloat162*)(lo + base + 2) = l23;
}

/* ------------------------------------------------------------------ */
__global__ void final_kernel(const float* __restrict__ V2,
                             const float* __restrict__ U,
                             float* __restrict__ out)
{
    int idx = blockIdx.x * 256 + threadIdx.x;
    const int off = (BLr * DM) >> 2;
    float4 a = ((const float4*)V2)[idx];
    float4 b = ((const float4*)V2)[idx + off];
    float4 c = ((const float4*)U)[idx];
    float4 d = ((const float4*)U)[idx + off];
    float4 o;
    o.x = a.x + b.x + c.x + d.x;
    o.y = a.y + b.y + c.y + d.y;
    o.z = a.z + b.z + c.z + d.z;
    o.w = a.w + b.w + c.w + d.w;
    ((float4*)out)[idx] = o;
}

/* ------------------------------------------------------------------ */
extern "C" void kernel_launch(void* const* d_in, const int* in_sizes, int n_in,
                              void* d_out, int out_size)
{
    (void)in_sizes; (void)n_in; (void)out_size;

    float *xz, *xc, *dbl, *part, *delta, *U, *V2, *hloc, *aprod, *hin;
    __nv_bfloat16 *Ahi, *Alo, *Bhi, *Blo;
    cudaGetSymbolAddress((void**)&xz,    g_xz);
    cudaGetSymbolAddress((void**)&xc,    g_xc);
    cudaGetSymbolAddress((void**)&dbl,   g_dbl);
    cudaGetSymbolAddress((void**)&part,  g_part);
    cudaGetSymbolAddress((void**)&delta, g_delta);
    cudaGetSymbolAddress((void**)&U,     g_U);
    cudaGetSymbolAddress((void**)&V2,    g_V2);
    cudaGetSymbolAddress((void**)&hloc,  g_hloc);
    cudaGetSymbolAddress((void**)&aprod, g_aprod);
    cudaGetSymbolAddress((void**)&hin,   g_hin);
    cudaGetSymbolAddress((void**)&Ahi,   g_Ahi);
    cudaGetSymbolAddress((void**)&Alo,   g_Alo);
    cudaGetSymbolAddress((void**)&Bhi,   g_Bhi);
    cudaGetSymbolAddress((void**)&Blo,   g_Blo);

    cudaFuncSetAttribute(mma_gemm, cudaFuncAttributeMaxDynamicSharedMemorySize,
                         MM_SMEM);

    const float* x = (const float*)d_in[0];
    const float* norm1_g = (const float*)d_in[19];
    const float* norm1_b = (const float*)d_in[20];
    const float* ffn_w1  = (const float*)d_in[23];
    const float* ffn_b1  = (const float*)d_in[24];
    const float* ffn_w2  = (const float*)d_in[25];
    const float* ffn_b2  = (const float*)d_in[26];

    const float* W[2][9];
    for (int dir = 0; dir < 2; ++dir)
        for (int k = 0; k < 9; ++k)
            W[dir][k] = (const float*)d_in[1 + dir * 9 + k];

    const size_t N_X   = (size_t)BLr * DM;        /* 2M  */
    const size_t N_Y   = (size_t)BLr * ED_;       /* 4M  */
    const size_t N_INW = (size_t)DM * 2 * ED_;    /* 1M  */
    const size_t N_OUW = (size_t)ED_ * DM;        /* 512K */
    const size_t N_FFW = (size_t)DM * DFF;        /* 512K */
    const size_t N_DT  = (size_t)BLr * DTR;       /* 128K per dir */
    const size_t OFF_U = 4 * N_X;                 /* U bf16 staging at 8M (within 12M buf) */

    /* stage GEMM1 operands: x straight+flipped (one launch), weights */
    cvt_x2_kernel<<<dim3((int)(N_X / 4 / 256), 1, 2), 256>>>(x, Ahi, Alo, N_X);
    cvt2_kernel<<<dim3((int)(N_INW / 4 / 256), 1, 2), 256>>>(
        W[0][0], W[1][0], Bhi, Blo, N_INW, (int)(N_INW / 4));

    /* GEMM1: xz = [x|xb] @ in_w : 4096x2048x512, z=2 */
    mma_gemm<<<dim3(2 * ED_ / 128, BLr / 128, 2), 256, MM_SMEM>>>(
        Ahi, Alo, N_X, Bhi, Blo, N_INW, 2 * ED_, DM,
        xz, (size_t)BLr * 2 * ED_, nullptr, nullptr, nullptr, nullptr, 0);

    /* conv + silu */
    conv_silu_kernel<<<dim3((BLr * ED_) / 256, 1, 2), 256>>>(
        xz, W[0][1], W[0][2], W[1][1], W[1][2], xc);

    /* xproj split-K + reduce */
    xproj_kernel<<<dim3(KSPL, BLr / 64, 2), 256>>>(xc, W[0][3], W[1][3], part);
    xproj_reduce<<<(2 * BLr * 64 / 4) / 256, 256>>>(part, dbl);

    /* delta = softplus(dt @ dt_w + dt_b) on tensor path (K=32) */
    cvt_dt_kernel<<<(2 * BLr * 8) / 256, 256>>>(dbl, Ahi, Alo);
    cvt2_kernel<<<dim3((int)(DTR * ED_ / 4 / 256), 1, 2), 256>>>(
        W[0][4], W[1][4], Bhi, Blo, (size_t)DTR * ED_, (int)(DTR * ED_ / 4));
    mma_gemm<<<dim3(ED_ / 128, BLr / 128, 2), 256, MM_SMEM>>>(
        Ahi, Alo, N_DT, Bhi, Blo, (size_t)DTR * ED_, ED_, DTR,
        delta, (size_t)BLr * ED_, nullptr, nullptr, W[0][5], W[1][5], 3);

    /* chunked scan (4 states/lane); scanC writes y bf16 hi/lo at 0 */
    scanA_kernel<<<dim3(512, 2), 256>>>(
        delta, xc, dbl, W[0][6], W[1][6], hloc, aprod);
    scanB_kernel<<<dim3(128, 2), 256>>>(hloc, aprod, hin);
    scanC_kernel<<<dim3(512, 2), 256>>>(
        delta, xc, dbl, xz, W[0][6], W[1][6], W[0][7], W[1][7], hin, Ahi, Alo);

    /* GEMM4: U = y @ out_w (fp32) + U bf16 hi/lo staged at OFF_U=8M */
    cvt2_kernel<<<dim3((int)(N_OUW / 4 / 256), 1, 2), 256>>>(
        W[0][8], W[1][8], Bhi, Blo, N_OUW, (int)(N_OUW / 4));
    mma_gemm<<<dim3(DM / 128, BLr / 128, 2), 256, MM_SMEM>>>(
        Ahi, Alo, N_Y, Bhi, Blo, N_OUW, DM, ED_,
        U, N_X, Ahi + OFF_U, Alo + OFF_U, nullptr, nullptr, 0);

    /* layernorm on forward branch (re-stages its bf16 hi/lo) */
    ln_kernel<<<BLr, 128>>>(U, norm1_g, norm1_b, Ahi + OFF_U, Alo + OFF_U);

    /* stage both FFN weights */
    cvt2_kernel<<<dim3((int)(N_FFW / 4 / 256), 1, 2), 256>>>(
        ffn_w1, ffn_w2, Bhi, Blo, N_FFW, (int)(N_FFW / 4));

    /* FFN1: Vh(hi/lo at 0..8M) = relu(U @ w1 + b1); A read at 8M..12M */
    mma_gemm<<<dim3(DFF / 128, 2 * BLr / 128, 1), 256, MM_SMEM>>>(
        Ahi + OFF_U, Alo + OFF_U, 0, Bhi, Blo, 0, DFF, DM,
        nullptr, 0, Ahi, Alo, ffn_b1, nullptr, 1);

    /* FFN2: V2 = Vh @ w2 + b2 */
    mma_gemm<<<dim3(DM / 128, 2 * BLr / 128, 1), 256, MM_SMEM>>>(
        Ahi, Alo, 0, Bhi + N_FFW, Blo + N_FFW, 0, DM, DFF,
        V2, 0, nullptr, nullptr, ffn_b2, nullptr, 2);

    /* out = V2_f + V2_b + U_f + U_b */
    final_kernel<<<(BLr * DM / 4) / 256, 256>>>(V2, U, (float*)d_out);
}

// round 16
// speedup vs baseline: 1.0149x; 1.0149x over previous
#include <cuda_runtime.h>
#include <cuda_bf16.h>
#include <cstdint>

#define Bb     2
#define LL     2048
#define DM     512
#define ED_    1024
#define NS     16
#define DTR    32
#define DFF    1024
#define BLr    (Bb*LL)            /* 4096 rows */
#define NCHUNK 16
#define CLEN   (LL/NCHUNK)        /* 128 */
#define NCHAIN 2048
#define KSPL   8

typedef unsigned long long ull;

/* ------------------------------------------------------------------ */
__device__ float g_xz   [2*BLr*2*ED_];
__device__ float g_xc   [2*BLr*ED_];
__device__ float g_dbl  [2*BLr*64];
__device__ float g_part [2*KSPL*BLr*64];
__device__ float g_delta[2*BLr*ED_];
__device__ float g_U    [2*BLr*DM];
__device__ float g_V2   [2*BLr*DM];
__device__ float g_hloc [2*NCHUNK*NCHAIN*NS];
__device__ float g_aprod[2*NCHUNK*NCHAIN*NS];
__device__ float g_hin  [2*NCHUNK*NCHAIN*NS];
__device__ __nv_bfloat16 g_Ahi[12*1024*1024];
__device__ __nv_bfloat16 g_Alo[12*1024*1024];
__device__ __nv_bfloat16 g_Bhi[2*1024*1024];
__device__ __nv_bfloat16 g_Blo[2*1024*1024];

/* ------------------------------------------------------------------ */
__device__ __forceinline__ float softplusf(float x) {
    return fmaxf(x, 0.f) + log1pf(expf(-fabsf(x)));
}
__device__ __forceinline__ float siluf(float x) {
    return x / (1.f + __expf(-x));
}
__device__ __forceinline__ uint32_t smem_u32(const void* p) {
    uint32_t a;
    asm("{ .reg .u64 t; cvta.to.shared.u64 t, %1; cvt.u32.u64 %0, t; }"
        : "=r"(a) : "l"(p));
    return a;
}
__device__ __forceinline__ ull fma2(ull a, ull b, ull c) {
    ull d;
    asm("fma.rn.f32x2 %0, %1, %2, %3;" : "=l"(d) : "l"(a), "l"(b), "l"(c));
    return d;
}
__device__ __forceinline__ ull packf2(float lo, float hi) {
    ull r;
    asm("mov.b64 %0, {%1, %2};" : "=l"(r) : "f"(lo), "f"(hi));
    return r;
}
__device__ __forceinline__ float2 unpackf2(ull v) {
    float lo, hi;
    asm("mov.b64 {%0, %1}, %2;" : "=f"(lo), "=f"(hi) : "l"(v));
    return make_float2(lo, hi);
}
__device__ __forceinline__ void cp16(uint32_t dst, const void* src) {
    asm volatile("cp.async.ca.shared.global [%0], [%1], 16;"
                 :: "r"(dst), "l"(src));
}
__device__ __forceinline__ void cp_commit() {
    asm volatile("cp.async.commit_group;");
}
__device__ __forceinline__ void cp_wait0() {
    asm volatile("cp.async.wait_group 0;" ::: "memory");
}

/* ================= HMMA helpers =================================== */
__device__ __forceinline__ void ldm_x4(uint32_t* r, uint32_t addr) {
    asm volatile("ldmatrix.sync.aligned.m8n8.x4.shared.b16 {%0,%1,%2,%3}, [%4];"
                 : "=r"(r[0]), "=r"(r[1]), "=r"(r[2]), "=r"(r[3]) : "r"(addr));
}
__device__ __forceinline__ void ldm_x4t(uint32_t* r, uint32_t addr) {
    asm volatile("ldmatrix.sync.aligned.m8n8.x4.trans.shared.b16 {%0,%1,%2,%3}, [%4];"
                 : "=r"(r[0]), "=r"(r[1]), "=r"(r[2]), "=r"(r[3]) : "r"(addr));
}
__device__ __forceinline__ void mma_bf16(float* c, const uint32_t* a,
                                         const uint32_t* b) {
    asm volatile(
        "mma.sync.aligned.m16n8k16.row.col.f32.bf16.bf16.f32 "
        "{%0,%1,%2,%3},{%4,%5,%6,%7},{%8,%9},{%0,%1,%2,%3};"
        : "+f"(c[0]), "+f"(c[1]), "+f"(c[2]), "+f"(c[3])
        : "r"(a[0]), "r"(a[1]), "r"(a[2]), "r"(a[3]), "r"(b[0]), "r"(b[1]));
}

/* ================= fp32 -> bf16 hi/lo convert ===================== */
__global__ void cvt_kernel(const float* __restrict__ s,
                           __nv_bfloat16* __restrict__ hi,
                           __nv_bfloat16* __restrict__ lo, int n4)
{
    int i = blockIdx.x * 256 + threadIdx.x;
    if (i >= n4) return;
    float4 v = ((const float4*)s)[i];
    __nv_bfloat162 h01 = __floats2bfloat162_rn(v.x, v.y);
    float2 f01 = __bfloat1622float2(h01);
    __nv_bfloat162 l01 = __floats2bfloat162_rn(v.x - f01.x, v.y - f01.y);
    __nv_bfloat162 h23 = __floats2bfloat162_rn(v.z, v.w);
    float2 f23 = __bfloat1622float2(h23);
    __nv_bfloat162 l23 = __floats2bfloat162_rn(v.z - f23.x, v.w - f23.y);
    ((__nv_bfloat162*)hi)[i * 2]     = h01;
    ((__nv_bfloat162*)hi)[i * 2 + 1] = h23;
    ((__nv_bfloat162*)lo)[i * 2]     = l01;
    ((__nv_bfloat162*)lo)[i * 2 + 1] = l23;
}

__global__ void cvt2_kernel(const float* __restrict__ s0,
                            const float* __restrict__ s1,
                            __nv_bfloat16* __restrict__ hi,
                            __nv_bfloat16* __restrict__ lo,
                            size_t stride, int n4)
{
    int i = blockIdx.x * 256 + threadIdx.x;
    if (i >= n4) return;
    const float* s = blockIdx.z ? s1 : s0;
    hi += blockIdx.z * stride;
    lo += blockIdx.z * stride;
    float4 v = ((const float4*)s)[i];
    __nv_bfloat162 h01 = __floats2bfloat162_rn(v.x, v.y);
    float2 f01 = __bfloat1622float2(h01);
    __nv_bfloat162 l01 = __floats2bfloat162_rn(v.x - f01.x, v.y - f01.y);
    __nv_bfloat162 h23 = __floats2bfloat162_rn(v.z, v.w);
    float2 f23 = __bfloat1622float2(h23);
    __nv_bfloat162 l23 = __floats2bfloat162_rn(v.z - f23.x, v.w - f23.y);
    ((__nv_bfloat162*)hi)[i * 2]     = h01;
    ((__nv_bfloat162*)hi)[i * 2 + 1] = h23;
    ((__nv_bfloat162*)lo)[i * 2]     = l01;
    ((__nv_bfloat162*)lo)[i * 2 + 1] = l23;
}

/* z0: straight x cvt; z1: L-flipped x cvt */
__global__ void cvt_x2_kernel(const float* __restrict__ s,
                              __nv_bfloat16* __restrict__ hi,
                              __nv_bfloat16* __restrict__ lo, size_t stride)
{
    int i = blockIdx.x * 256 + threadIdx.x;
    hi += blockIdx.z * stride;
    lo += blockIdx.z * stride;
    float4 v;
    if (blockIdx.z == 0) {
        v = ((const float4*)s)[i];
    } else {
        int c = i & 127;
        int r = i >> 7;
        int b = r >> 11;
        int l = r & 2047;
        v = ((const float4*)s)[(size_t)(((b << 11) + (2047 - l)) << 7) + c];
    }
    __nv_bfloat162 h01 = __floats2bfloat162_rn(v.x, v.y);
    float2 f01 = __bfloat1622float2(h01);
    __nv_bfloat162 l01 = __floats2bfloat162_rn(v.x - f01.x, v.y - f01.y);
    __nv_bfloat162 h23 = __floats2bfloat162_rn(v.z, v.w);
    float2 f23 = __bfloat1622float2(h23);
    __nv_bfloat162 l23 = __floats2bfloat162_rn(v.z - f23.x, v.w - f23.y);
    ((__nv_bfloat162*)hi)[i * 2]     = h01;
    ((__nv_bfloat162*)hi)[i * 2 + 1] = h23;
    ((__nv_bfloat162*)lo)[i * 2]     = l01;
    ((__nv_bfloat162*)lo)[i * 2 + 1] = l23;
}

/* ======== split-bf16 HMMA GEMM, 2-stage cp.async, occ 2 =========== */
/* ep: 0 none, 1 bias+relu, 2 bias                                    */
#define OFF_ALO 10240
#define OFF_BHI 20480
#define OFF_BLO 29184
#define MBUF    37888
#define MM_SMEM (2*MBUF)

__global__ void __launch_bounds__(256, 2)
mma_gemm(const __nv_bfloat16* __restrict__ Ah,
         const __nv_bfloat16* __restrict__ Al, size_t sA,
         const __nv_bfloat16* __restrict__ Bh,
         const __nv_bfloat16* __restrict__ Bl, size_t sB,
         int N, int K,
         float* __restrict__ C, size_t sC,
         __nv_bfloat16* __restrict__ Chi, __nv_bfloat16* __restrict__ Clo,
         const float* __restrict__ bias, int ep)
{
    extern __shared__ char smc[];
    const int z = blockIdx.z;
    Ah += (size_t)z * sA;  Al += (size_t)z * sA;
    Bh += (size_t)z * sB;  Bl += (size_t)z * sB;
    if (C)   C   += (size_t)z * sC;
    if (Chi) { Chi += (size_t)z * sC; Clo += (size_t)z * sC; }

    const int tid  = threadIdx.x;
    const int lane = tid & 31;
    const int wid  = tid >> 5;
    const int wm   = wid & 1;
    const int wn   = wid >> 1;
    const int m0 = blockIdx.y * 128;
    const int n0 = blockIdx.x * 128;

    const int a_row = tid >> 2;
    const int a_ch  = tid & 3;
    const int b_row = tid >> 4;
    const int b_ch  = tid & 15;

    const __nv_bfloat16* gA0h = Ah + (size_t)(m0 + a_row) * K + a_ch * 8;
    const __nv_bfloat16* gA1h = gA0h + (size_t)64 * K;
    const __nv_bfloat16* gA0l = Al + (size_t)(m0 + a_row) * K + a_ch * 8;
    const __nv_bfloat16* gA1l = gA0l + (size_t)64 * K;
    const __nv_bfloat16* gB0h = Bh + (size_t)b_row * N + n0 + b_ch * 8;
    const __nv_bfloat16* gB1h = gB0h + (size_t)16 * N;
    const __nv_bfloat16* gB0l = Bl + (size_t)b_row * N + n0 + b_ch * 8;
    const __nv_bfloat16* gB1l = gB0l + (size_t)16 * N;

    const uint32_t sbase = smem_u32(smc);
    const uint32_t sa0 = (uint32_t)(a_row * 80 + a_ch * 16);
    const uint32_t sa1 = (uint32_t)((a_row + 64) * 80 + a_ch * 16);
    const uint32_t sb0 = (uint32_t)(b_row * 272 + b_ch * 16);
    const uint32_t sb1 = (uint32_t)((b_row + 16) * 272 + b_ch * 16);

    float acc[4][4][4];
#pragma unroll
    for (int i = 0; i < 4; ++i)
#pragma unroll
        for (int j = 0; j < 4; ++j)
#pragma unroll
            for (int q = 0; q < 4; ++q) acc[i][j][q] = 0.f;

    /* prolog: tile 0 via cp.async */
    {
        const uint32_t d = sbase;
        cp16(d + sa0, gA0h);            cp16(d + sa1, gA1h);
        cp16(d + OFF_ALO + sa0, gA0l);  cp16(d + OFF_ALO + sa1, gA1l);
        cp16(d + OFF_BHI + sb0, gB0h);  cp16(d + OFF_BHI + sb1, gB1h);
        cp16(d + OFF_BLO + sb0, gB0l);  cp16(d + OFF_BLO + sb1, gB1l);
        cp_commit();
        cp_wait0();
    }
    __syncthreads();

    const int NIT = K >> 5;
    for (int it = 0; it < NIT; ++it) {
        if (it + 1 < NIT) {
            const int kq = (it + 1) << 5;
            const size_t bo = (size_t)kq * N;
            const uint32_t d = sbase + (uint32_t)(((it + 1) & 1) * MBUF);
            cp16(d + sa0, gA0h + kq);            cp16(d + sa1, gA1h + kq);
            cp16(d + OFF_ALO + sa0, gA0l + kq);  cp16(d + OFF_ALO + sa1, gA1l + kq);
            cp16(d + OFF_BHI + sb0, gB0h + bo);  cp16(d + OFF_BHI + sb1, gB1h + bo);
            cp16(d + OFF_BLO + sb0, gB0l + bo);  cp16(d + OFF_BLO + sb1, gB1l + bo);
            cp_commit();
        }

        const uint32_t base = sbase + (uint32_t)((it & 1) * MBUF);
#pragma unroll
        for (int ks = 0; ks < 2; ++ks) {
            uint32_t ah[4][4], al[4][4], bh[2][4], bl[2][4];
            uint32_t aaddr = base + (uint32_t)((wm * 64 + (lane & 15)) * 80
                               + ks * 32 + ((lane >> 4) & 1) * 16);
#pragma unroll
            for (int mf = 0; mf < 4; ++mf) {
                ldm_x4(ah[mf], aaddr + mf * 1280);
                ldm_x4(al[mf], aaddr + OFF_ALO + mf * 1280);
            }
            uint32_t baddr = base + OFF_BHI
                + (uint32_t)((ks * 16 + (lane & 15)) * 272
                + (wn * 32 + ((lane >> 4) & 1) * 8) * 2);
#pragma unroll
            for (int np = 0; np < 2; ++np) {
                ldm_x4t(bh[np], baddr + np * 32);
                ldm_x4t(bl[np], baddr + (OFF_BLO - OFF_BHI) + np * 32);
            }
#pragma unroll
            for (int mf = 0; mf < 4; ++mf)
#pragma unroll
                for (int nf = 0; nf < 4; ++nf) {
                    const uint32_t* bhp = &bh[nf >> 1][(nf & 1) * 2];
                    const uint32_t* blp = &bl[nf >> 1][(nf & 1) * 2];
                    mma_bf16(acc[mf][nf], ah[mf], bhp);
                    mma_bf16(acc[mf][nf], ah[mf], blp);
                    mma_bf16(acc[mf][nf], al[mf], bhp);
                }
        }

        if (it + 1 < NIT) cp_wait0();
        __syncthreads();
    }

    /* ---- epilogue ---- */
    const int row = m0 + wm * 64 + (lane >> 2);
    const int col = n0 + wn * 32 + (lane & 3) * 2;
#pragma unroll
    for (int nf = 0; nf < 4; ++nf) {
        const int c = col + nf * 8;
        float2 bv = make_float2(0.f, 0.f);
        if (ep) bv = *(const float2*)(bias + c);
#pragma unroll
        for (int mf = 0; mf < 4; ++mf) {
            const int r = row + mf * 16;
            float2 v0 = make_float2(acc[mf][nf][0] + bv.x, acc[mf][nf][1] + bv.y);
            float2 v1 = make_float2(acc[mf][nf][2] + bv.x, acc[mf][nf][3] + bv.y);
            if (ep == 1) {
                v0.x = fmaxf(v0.x, 0.f); v0.y = fmaxf(v0.y, 0.f);
                v1.x = fmaxf(v1.x, 0.f); v1.y = fmaxf(v1.y, 0.f);
            }
            if (C) {
                *(float2*)(C + (size_t)r * N + c)       = v0;
                *(float2*)(C + (size_t)(r + 8) * N + c) = v1;
            }
            if (Chi) {
                __nv_bfloat162 h0 = __floats2bfloat162_rn(v0.x, v0.y);
                float2 f0 = __bfloat1622float2(h0);
                __nv_bfloat162 l0 = __floats2bfloat162_rn(v0.x - f0.x, v0.y - f0.y);
                __nv_bfloat162 h1 = __floats2bfloat162_rn(v1.x, v1.y);
                float2 f1 = __bfloat1622float2(h1);
                __nv_bfloat162 l1 = __floats2bfloat162_rn(v1.x - f1.x, v1.y - f1.y);
                *(__nv_bfloat162*)(Chi + (size_t)r * N + c)       = h0;
                *(__nv_bfloat162*)(Chi + (size_t)(r + 8) * N + c) = h1;
                *(__nv_bfloat162*)(Clo + (size_t)r * N + c)       = l0;
                *(__nv_bfloat162*)(Clo + (size_t)(r + 8) * N + c) = l1;
            }
        }
    }
}

/* ================= f32x2 GEMM (delta only) ========================= */
__global__ void __launch_bounds__(256, 2)
f2_gemm(const float* __restrict__ A0, const float* __restrict__ A1, int lda,
        const float* __restrict__ B0, const float* __restrict__ B1,
        int N, int K,
        float* __restrict__ C, size_t strideC,
        const float* __restrict__ bias0, const float* __restrict__ bias1,
        int ep)
{
    __shared__ float As[2][16][132];
    __shared__ float Bs[2][16][132];

    const int z = blockIdx.z;
    const float* A = z ? A1 : A0;
    const float* B = z ? B1 : B0;
    const float* bias = z ? bias1 : bias0;
    C += (size_t)z * strideC;

    const int tid = threadIdx.x;
    const int m0 = blockIdx.y * 128;
    const int n0 = blockIdx.x * 128;
    const int tm = tid >> 4;
    const int tn = tid & 15;

    const int arow = tid >> 1;
    const int acol = (tid & 1) * 8;
    const int brow = tid >> 4;
    const int bcol = (tid & 15) * 8;

    const float* gA = A + (size_t)(m0 + arow) * lda + acol;
    const float* gB = B + (size_t)brow * N + n0 + bcol;
    const uint32_t bs0 = smem_u32(&Bs[0][0][0]) + (uint32_t)((brow * 132 + bcol) * 4);
    const uint32_t bsStride = 16u * 132u * 4u;

    float4 a0, a1;

    a0 = *(const float4*)gA;  a1 = *(const float4*)(gA + 4);
    As[0][acol + 0][arow] = a0.x;  As[0][acol + 1][arow] = a0.y;
    As[0][acol + 2][arow] = a0.z;  As[0][acol + 3][arow] = a0.w;
    As[0][acol + 4][arow] = a1.x;  As[0][acol + 5][arow] = a1.y;
    As[0][acol + 6][arow] = a1.z;  As[0][acol + 7][arow] = a1.w;
    cp16(bs0,      gB);
    cp16(bs0 + 16, gB + 4);
    cp_commit();
    cp_wait0();
    __syncthreads();

    ull acc[8][4];
#pragma unroll
    for (int i = 0; i < 8; ++i)
#pragma unroll
        for (int j = 0; j < 4; ++j) acc[i][j] = 0ull;

    const int NIT = K >> 4;
    for (int it = 0; it < NIT; ++it) {
        const int buf = it & 1;
        if (it + 1 < NIT) {
            const float* pA = gA + (it + 1) * 16;
            a0 = *(const float4*)pA;  a1 = *(const float4*)(pA + 4);
            const float* pB = gB + (size_t)(it + 1) * 16 * N;
            const uint32_t d = bs0 + (buf ^ 1) * bsStride;
            cp16(d,      pB);
            cp16(d + 16, pB + 4);
            cp_commit();
        }
#pragma unroll
        for (int k = 0; k < 16; ++k) {
            float4 f0 = *(const float4*)&As[buf][k][tm * 8];
            float4 f1 = *(const float4*)&As[buf][k][tm * 8 + 4];
            ull a2[8];
            a2[0] = packf2(f0.x, f0.x);  a2[1] = packf2(f0.y, f0.y);
            a2[2] = packf2(f0.z, f0.z);  a2[3] = packf2(f0.w, f0.w);
            a2[4] = packf2(f1.x, f1.x);  a2[5] = packf2(f1.y, f1.y);
            a2[6] = packf2(f1.z, f1.z);  a2[7] = packf2(f1.w, f1.w);
            ull b2[4];
#pragma unroll
            for (int jj = 0; jj < 4; ++jj)
                b2[jj] = *(const ull*)&Bs[buf][k][tn * 2 + 32 * jj];
#pragma unroll
            for (int i = 0; i < 8; ++i)
#pragma unroll
                for (int jj = 0; jj < 4; ++jj)
                    acc[i][jj] = fma2(a2[i], b2[jj], acc[i][jj]);
        }
        if (it + 1 < NIT) {
            const int nb = buf ^ 1;
            As[nb][acol + 0][arow] = a0.x;  As[nb][acol + 1][arow] = a0.y;
            As[nb][acol + 2][arow] = a0.z;  As[nb][acol + 3][arow] = a0.w;
            As[nb][acol + 4][arow] = a1.x;  As[nb][acol + 5][arow] = a1.y;
            As[nb][acol + 6][arow] = a1.z;  As[nb][acol + 7][arow] = a1.w;
            cp_wait0();
        }
        __syncthreads();
    }

    const int crow = m0 + tm * 8;
    float2 bv[4];
#pragma unroll
    for (int jj = 0; jj < 4; ++jj) {
        if (ep) bv[jj] = *(const float2*)(bias + n0 + tn * 2 + 32 * jj);
        else    bv[jj] = make_float2(0.f, 0.f);
    }
#pragma unroll
    for (int i = 0; i < 8; ++i) {
        float* Crow = C + (size_t)(crow + i) * N + n0 + tn * 2;
#pragma unroll
        for (int jj = 0; jj < 4; ++jj) {
            float2 v = unpackf2(acc[i][jj]);
            v.x += bv[jj].x;  v.y += bv[jj].y;
            if (ep == 1) {
                v.x = fmaxf(v.x, 0.f);  v.y = fmaxf(v.y, 0.f);
            } else if (ep == 3) {
                v.x = softplusf(v.x);   v.y = softplusf(v.y);
            }
            *(float2*)(Crow + 32 * jj) = v;
        }
    }
}

/* ================= xproj split-K ==================================== */
__global__ __launch_bounds__(256)
void xproj_kernel(const float* __restrict__ xc,
                  const float* __restrict__ B0, const float* __restrict__ B1,
                  float* __restrict__ part)
{
    __shared__ float As[16][68];
    __shared__ float Bs[16][68];

    const int ks  = blockIdx.x;
    const int dir = blockIdx.z;
    const float* A = xc + (size_t)dir * BLr * ED_;
    const float* B = dir ? B1 : B0;
    float* P = part + ((size_t)dir * KSPL + ks) * BLr * 64;

    const int tid  = threadIdx.x;
    const int tx   = tid & 15;
    const int ty   = tid >> 4;
    const int row0 = blockIdx.y * 64;
    const int kbase = ks * (ED_ / KSPL);

    const int ar = tid >> 2;
    const int ak = (tid & 3) << 2;
    const int bk = tid >> 4;
    const int bn = (tid & 15) << 2;

    float acc[4][4];
#pragma unroll
    for (int i = 0; i < 4; ++i)
#pragma unroll
        for (int j = 0; j < 4; ++j) acc[i][j] = 0.f;

    for (int k0 = kbase; k0 < kbase + ED_ / KSPL; k0 += 16) {
        float4 avv = *(const float4*)(A + (size_t)(row0 + ar) * ED_ + k0 + ak);
        As[ak + 0][ar] = avv.x;
        As[ak + 1][ar] = avv.y;
        As[ak + 2][ar] = avv.z;
        As[ak + 3][ar] = avv.w;
        *(float4*)&Bs[bk][bn] =
            *(const float4*)(B + (size_t)(k0 + bk) * 64 + bn);
        __syncthreads();

#pragma unroll
        for (int kk = 0; kk < 16; ++kk) {
            float4 a = *(const float4*)&As[kk][ty << 2];
            float4 b = *(const float4*)&Bs[kk][tx << 2];
            float ai[4] = {a.x, a.y, a.z, a.w};
            float bj[4] = {b.x, b.y, b.z, b.w};
#pragma unroll
            for (int i = 0; i < 4; ++i)
#pragma unroll
                for (int j = 0; j < 4; ++j)
                    acc[i][j] = fmaf(ai[i], bj[j], acc[i][j]);
        }
        __syncthreads();
    }

    const int m0 = row0 + (ty << 2);
    const int n0 = tx << 2;
#pragma unroll
    for (int i = 0; i < 4; ++i)
        *(float4*)(P + (size_t)(m0 + i) * 64 + n0) =
            make_float4(acc[i][0], acc[i][1], acc[i][2], acc[i][3]);
}

__global__ void xproj_reduce(const float* __restrict__ part,
                             float* __restrict__ dbl)
{
    const int idx = blockIdx.x * 256 + threadIdx.x;
    const int dir = idx >> 16;
    const int r   = idx & 65535;
    const float4* p = (const float4*)part + (size_t)dir * KSPL * 65536 + r;
    float4 s = make_float4(0.f, 0.f, 0.f, 0.f);
#pragma unroll
    for (int ks = 0; ks < KSPL; ++ks) {
        float4 v = p[(size_t)ks * 65536];
        s.x += v.x; s.y += v.y; s.z += v.z; s.w += v.w;
    }
    ((float4*)dbl)[idx] = s;
}

/* ------------------------------------------------------------------ */
__global__ void conv_silu_kernel(const float* __restrict__ xz,
                                 const float* __restrict__ cw0,
                                 const float* __restrict__ cb0,
                                 const float* __restrict__ cw1,
                                 const float* __restrict__ cb1,
                                 float* __restrict__ xc)
{
    const int dir = blockIdx.z;
    const float* cw = dir ? cw1 : cw0;
    const float* cb = dir ? cb1 : cb0;
    xz += (size_t)dir * BLr * 2 * ED_;
    xc += (size_t)dir * BLr * ED_;

    int idx = blockIdx.x * 256 + threadIdx.x;
    int e = idx & 1023;
    int r = idx >> 10;
    int l = r & 2047;
    int b = r >> 11;
    float s = cb[e];
#pragma unroll
    for (int k = 0; k < 4; ++k) {
        int ll = l + k - 3;
        if (ll >= 0)
            s = fmaf(xz[((size_t)((b << 11) + ll) << 11) + e], cw[(e << 2) + k], s);
    }
    xc[idx] = siluf(s);
}

/* ================= chunked selective scan (4 states/lane) ========== */
__global__ __launch_bounds__(256)
void scanA_kernel(const float* __restrict__ delta,
                  const float* __restrict__ xc,
                  const float* __restrict__ dbl,
                  const float* __restrict__ Alog0,
                  const float* __restrict__ Alog1,
                  float* __restrict__ hloc, float* __restrict__ aprod)
{
    const int dir  = blockIdx.y;
    const int warp = blockIdx.x * 8 + (threadIdx.x >> 5);
    const int lane = threadIdx.x & 31;
    const int c    = lane >> 2;
    const int g    = lane & 3;
    const int chunk = warp >> 8;
    const int cg    = warp & 255;
    const int chain = cg * 8 + c;
    const int b = chain >> 10;
    const int e = chain & 1023;

    const float* Alog = dir ? Alog1 : Alog0;
    delta += (size_t)dir * BLr * ED_;
    xc    += (size_t)dir * BLr * ED_;
    dbl   += (size_t)dir * BLr * 64;

    float4 alv = *(const float4*)&Alog[(e << 4) + g * 4];
    const float a0 = -expf(alv.x), a1 = -expf(alv.y),
                a2 = -expf(alv.z), a3 = -expf(alv.w);
    float h0 = 0.f, h1 = 0.f, h2 = 0.f, h3 = 0.f;
    float p0 = 1.f, p1 = 1.f, p2 = 1.f, p3 = 1.f;
    const int r0 = (b << 11) + chunk * CLEN;

    for (int l = 0; l < CLEN; l += 4) {
        float d[4], xv[4];
        float4 bv[4];
#pragma unroll
        for (int s = 0; s < 4; ++s) {
            int row = r0 + l + s;
            d[s]  = __ldg(&delta[((size_t)row << 10) + e]);
            xv[s] = __ldg(&xc   [((size_t)row << 10) + e]);
            bv[s] = *(const float4*)&dbl[(row << 6) + 32 + g * 4];
        }
#pragma unroll
        for (int s = 0; s < 4; ++s) {
            const float t = d[s] * xv[s];
            float dA;
            dA = __expf(d[s] * a0); h0 = fmaf(dA, h0, t * bv[s].x); p0 *= dA;
            dA = __expf(d[s] * a1); h1 = fmaf(dA, h1, t * bv[s].y); p1 *= dA;
            dA = __expf(d[s] * a2); h2 = fmaf(dA, h2, t * bv[s].z); p2 *= dA;
            dA = __expf(d[s] * a3); h3 = fmaf(dA, h3, t * bv[s].w); p3 *= dA;
        }
    }
    size_t idx = ((size_t)dir * NCHUNK + chunk) * (NCHAIN * NS)
               + (size_t)chain * NS + g * 4;
    *(float4*)&hloc[idx]  = make_float4(h0, h1, h2, h3);
    *(float4*)&aprod[idx] = make_float4(p0, p1, p2, p3);
}

__global__ void scanB_kernel(const float* __restrict__ hloc,
                             const float* __restrict__ aprod,
                             float* __restrict__ hin)
{
    const int dir = blockIdx.y;
    const int t = blockIdx.x * 256 + threadIdx.x;
    const size_t base = (size_t)dir * NCHUNK * NCHAIN * NS;
    float h = 0.f;
#pragma unroll
    for (int c = 0; c < NCHUNK; ++c) {
        size_t idx = base + (size_t)c * NCHAIN * NS + t;
        hin[idx] = h;
        h = fmaf(aprod[idx], h, hloc[idx]);
    }
}

__global__ __launch_bounds__(256)
void scanC_kernel(const float* __restrict__ delta,
                  const float* __restrict__ xc,
                  const float* __restrict__ dbl,
                  const float* __restrict__ xz,
                  const float* __restrict__ Alog0,
                  const float* __restrict__ Alog1,
                  const float* __restrict__ Dp0,
                  const float* __restrict__ Dp1,
                  const float* __restrict__ hin,
                  __nv_bfloat16* __restrict__ yhi,
                  __nv_bfloat16* __restrict__ ylo)
{
    const int dir  = blockIdx.y;
    const int warp = blockIdx.x * 8 + (threadIdx.x >> 5);
    const int lane = threadIdx.x & 31;
    const int c    = lane >> 2;
    const int g    = lane & 3;
    const int chunk = warp >> 8;
    const int cg    = warp & 255;
    const int chain = cg * 8 + c;
    const int b = chain >> 10;
    const int e = chain & 1023;

    const float* Alog = dir ? Alog1 : Alog0;
    const float* Dp   = dir ? Dp1   : Dp0;
    delta += (size_t)dir * BLr * ED_;
    xc    += (size_t)dir * BLr * ED_;
    yhi   += (size_t)dir * BLr * ED_;
    ylo   += (size_t)dir * BLr * ED_;
    dbl   += (size_t)dir * BLr * 64;
    xz    += (size_t)dir * BLr * 2 * ED_;

    float4 alv = *(const float4*)&Alog[(e << 4) + g * 4];
    const float a0 = -expf(alv.x), a1 = -expf(alv.y),
                a2 = -expf(alv.z), a3 = -expf(alv.w);
    const float dc = Dp[e];
    float4 hv = *(const float4*)&hin[((size_t)dir * NCHUNK + chunk)
               * (NCHAIN * NS) + (size_t)chain * NS + g * 4];
    float h0 = hv.x, h1 = hv.y, h2 = hv.z, h3 = hv.w;
    const int r0 = (b << 11) + chunk * CLEN;

    for (int l = 0; l < CLEN; l += 4) {
        float d[4], xv[4];
        float4 bv[4], cv[4];
#pragma unroll
        for (int s = 0; s < 4; ++s) {
            int row = r0 + l + s;
            d[s]  = __ldg(&delta[((size_t)row << 10) + e]);
            xv[s] = __ldg(&xc   [((size_t)row << 10) + e]);
            bv[s] = *(const float4*)&dbl[(row << 6) + 32 + g * 4];
            cv[s] = *(const float4*)&dbl[(row << 6) + 48 + g * 4];
        }
        float p[4];
#pragma unroll
        for (int s = 0; s < 4; ++s) {
            const float t = d[s] * xv[s];
            float dA;
            dA = __expf(d[s] * a0); h0 = fmaf(dA, h0, t * bv[s].x);
            dA = __expf(d[s] * a1); h1 = fmaf(dA, h1, t * bv[s].y);
            dA = __expf(d[s] * a2); h2 = fmaf(dA, h2, t * bv[s].z);
            dA = __expf(d[s] * a3); h3 = fmaf(dA, h3, t * bv[s].w);
            p[s] = h0 * cv[s].x + h1 * cv[s].y + h2 * cv[s].z + h3 * cv[s].w;
        }
#pragma unroll
        for (int s = 0; s < 4; ++s) {
            p[s] += __shfl_xor_sync(0xffffffffu, p[s], 1);
            p[s] += __shfl_xor_sync(0xffffffffu, p[s], 2);
        }
        if (g == 0) {
#pragma unroll
            for (int s = 0; s < 4; ++s) {
                int row = r0 + l + s;
                float zv = xz[((size_t)row << 11) + 1024 + e];
                float val = (p[s] + xv[s] * dc) * siluf(zv);
                __nv_bfloat16 hb = __float2bfloat16_rn(val);
                yhi[((size_t)row << 10) + e] = hb;
                ylo[((size_t)row << 10) + e] =
                    __float2bfloat16_rn(val - __bfloat162float(hb));
            }
        }
    }
}

/* ---- layernorm; also emits bf16 hi/lo of the result -------------- */
__global__ __launch_bounds__(128)
void ln_kernel(float* __restrict__ U, const float* __restrict__ g,
               const float* __restrict__ bb,
               __nv_bfloat16* __restrict__ hi, __nv_bfloat16* __restrict__ lo)
{
    int row = blockIdx.x;
    float4* p = (float4*)(U + (size_t)row * DM);
    int tid = threadIdx.x;
    int lane = tid & 31, w = tid >> 5;
    __shared__ float red[4];

    float4 v = p[tid];
    float s = v.x + v.y + v.z + v.w;
#pragma unroll
    for (int o = 16; o; o >>= 1) s += __shfl_xor_sync(0xffffffffu, s, o);
    if (!lane) red[w] = s;
    __syncthreads();
    float mu = (red[0] + red[1] + red[2] + red[3]) * (1.f / 512.f);

    float dx = v.x - mu, dy = v.y - mu, dz = v.z - mu, dw = v.w - mu;
    float s2 = dx*dx + dy*dy + dz*dz + dw*dw;
#pragma unroll
    for (int o = 16; o; o >>= 1) s2 += __shfl_xor_sync(0xffffffffu, s2, o);
    __syncthreads();
    if (!lane) red[w] = s2;
    __syncthreads();
    float var  = (red[0] + red[1] + red[2] + red[3]) * (1.f / 512.f);
    float rstd = rsqrtf(var + 1e-5f);

    int c = tid << 2;
    float4 go = *(const float4*)(g + c);
    float4 bo = *(const float4*)(bb + c);
    float4 o;
    o.x = dx * rstd * go.x + bo.x;
    o.y = dy * rstd * go.y + bo.y;
    o.z = dz * rstd * go.z + bo.z;
    o.w = dw * rstd * go.w + bo.w;
    p[tid] = o;

    __nv_bfloat162 h01 = __floats2bfloat162_rn(o.x, o.y);
    float2 f01 = __bfloat1622float2(h01);
    __nv_bfloat162 l01 = __floats2bfloat162_rn(o.x - f01.x, o.y - f01.y);
    __nv_bfloat162 h23 = __floats2bfloat162_rn(o.z, o.w);
    float2 f23 = __bfloat1622float2(h23);
    __nv_bfloat162 l23 = __floats2bfloat162_rn(o.z - f23.x, o.w - f23.y);
    size_t base = (size_t)row * DM + c;
    *(__nv_bfloat162*)(hi + base)     = h01;
    *(__nv_bfloat162*)(hi + base + 2) = h23;
    *(__nv_bfloat162*)(lo + base)     = l01;
    *(__nv_bfloat162*)(lo + base + 2) = l23;
}

/* ------------------------------------------------------------------ */
__global__ void final_kernel(const float* __restrict__ V2,
                             const float* __restrict__ U,
                             float* __restrict__ out)
{
    int idx = blockIdx.x * 256 + threadIdx.x;
    const int off = (BLr * DM) >> 2;
    float4 a = ((const float4*)V2)[idx];
    float4 b = ((const float4*)V2)[idx + off];
    float4 c = ((const float4*)U)[idx];
    float4 d = ((const float4*)U)[idx + off];
    float4 o;
    o.x = a.x + b.x + c.x + d.x;
    o.y = a.y + b.y + c.y + d.y;
    o.z = a.z + b.z + c.z + d.z;
    o.w = a.w + b.w + c.w + d.w;
    ((float4*)out)[idx] = o;
}

/* ------------------------------------------------------------------ */
extern "C" void kernel_launch(void* const* d_in, const int* in_sizes, int n_in,
                              void* d_out, int out_size)
{
    (void)in_sizes; (void)n_in; (void)out_size;

    float *xz, *xc, *dbl, *part, *delta, *U, *V2, *hloc, *aprod, *hin;
    __nv_bfloat16 *Ahi, *Alo, *Bhi, *Blo;
    cudaGetSymbolAddress((void**)&xz,    g_xz);
    cudaGetSymbolAddress((void**)&xc,    g_xc);
    cudaGetSymbolAddress((void**)&dbl,   g_dbl);
    cudaGetSymbolAddress((void**)&part,  g_part);
    cudaGetSymbolAddress((void**)&delta, g_delta);
    cudaGetSymbolAddress((void**)&U,     g_U);
    cudaGetSymbolAddress((void**)&V2,    g_V2);
    cudaGetSymbolAddress((void**)&hloc,  g_hloc);
    cudaGetSymbolAddress((void**)&aprod, g_aprod);
    cudaGetSymbolAddress((void**)&hin,   g_hin);
    cudaGetSymbolAddress((void**)&Ahi,   g_Ahi);
    cudaGetSymbolAddress((void**)&Alo,   g_Alo);
    cudaGetSymbolAddress((void**)&Bhi,   g_Bhi);
    cudaGetSymbolAddress((void**)&Blo,   g_Blo);

    cudaFuncSetAttribute(mma_gemm, cudaFuncAttributeMaxDynamicSharedMemorySize,
                         MM_SMEM);

    const float* x = (const float*)d_in[0];
    const float* norm1_g = (const float*)d_in[19];
    const float* norm1_b = (const float*)d_in[20];
    const float* ffn_w1  = (const float*)d_in[23];
    const float* ffn_b1  = (const float*)d_in[24];
    const float* ffn_w2  = (const float*)d_in[25];
    const float* ffn_b2  = (const float*)d_in[26];

    const float* W[2][9];
    for (int dir = 0; dir < 2; ++dir)
        for (int k = 0; k < 9; ++k)
            W[dir][k] = (const float*)d_in[1 + dir * 9 + k];

    const size_t N_X   = (size_t)BLr * DM;        /* 2M  */
    const size_t N_Y   = (size_t)BLr * ED_;       /* 4M  */
    const size_t N_INW = (size_t)DM * 2 * ED_;    /* 1M  */
    const size_t N_OUW = (size_t)ED_ * DM;        /* 512K */
    const size_t N_FFW = (size_t)DM * DFF;        /* 512K */
    const size_t OFF_U = 4 * N_X;                 /* U bf16 staging at 8M */

    /* stage GEMM1 operands: x straight+flipped (one launch), weights */
    cvt_x2_kernel<<<dim3((int)(N_X / 4 / 256), 1, 2), 256>>>(x, Ahi, Alo, N_X);
    cvt2_kernel<<<dim3((int)(N_INW / 4 / 256), 1, 2), 256>>>(
        W[0][0], W[1][0], Bhi, Blo, N_INW, (int)(N_INW / 4));

    /* GEMM1: xz = [x|xb] @ in_w : 4096x2048x512, z=2 */
    mma_gemm<<<dim3(2 * ED_ / 128, BLr / 128, 2), 256, MM_SMEM>>>(
        Ahi, Alo, N_X, Bhi, Blo, N_INW, 2 * ED_, DM,
        xz, (size_t)BLr * 2 * ED_, nullptr, nullptr, nullptr, 0);

    /* conv + silu */
    conv_silu_kernel<<<dim3((BLr * ED_) / 256, 1, 2), 256>>>(
        xz, W[0][1], W[0][2], W[1][1], W[1][2], xc);

    /* xproj split-K + reduce */
    xproj_kernel<<<dim3(KSPL, BLr / 64, 2), 256>>>(xc, W[0][3], W[1][3], part);
    xproj_reduce<<<(2 * BLr * 64 / 4) / 256, 256>>>(part, dbl);

    /* delta = softplus(dt @ dt_w + dt_b) : f32x2 path (K=32) */
    f2_gemm<<<dim3(ED_ / 128, BLr / 128, 2), 256>>>(
        dbl, dbl + (size_t)BLr * 64, 64, W[0][4], W[1][4], ED_, DTR,
        delta, (size_t)BLr * ED_, W[0][5], W[1][5], 3);

    /* chunked scan (4 states/lane); scanC writes y bf16 hi/lo at 0 */
    scanA_kernel<<<dim3(512, 2), 256>>>(
        delta, xc, dbl, W[0][6], W[1][6], hloc, aprod);
    scanB_kernel<<<dim3(128, 2), 256>>>(hloc, aprod, hin);
    scanC_kernel<<<dim3(512, 2), 256>>>(
        delta, xc, dbl, xz, W[0][6], W[1][6], W[0][7], W[1][7], hin, Ahi, Alo);

    /* GEMM4: U = y @ out_w (fp32) + U bf16 hi/lo staged at OFF_U */
    cvt2_kernel<<<dim3((int)(N_OUW / 4 / 256), 1, 2), 256>>>(
        W[0][8], W[1][8], Bhi, Blo, N_OUW, (int)(N_OUW / 4));
    mma_gemm<<<dim3(DM / 128, BLr / 128, 2), 256, MM_SMEM>>>(
        Ahi, Alo, N_Y, Bhi, Blo, N_OUW, DM, ED_,
        U, N_X, Ahi + OFF_U, Alo + OFF_U, nullptr, 0);

    /* layernorm on forward branch (re-stages its bf16 hi/lo) */
    ln_kernel<<<BLr, 128>>>(U, norm1_g, norm1_b, Ahi + OFF_U, Alo + OFF_U);

    /* stage both FFN weights */
    cvt2_kernel<<<dim3((int)(N_FFW / 4 / 256), 1, 2), 256>>>(
        ffn_w1, ffn_w2, Bhi, Blo, N_FFW, (int)(N_FFW / 4));

    /* FFN1: Vh(hi/lo at 0..8M) = relu(U @ w1 + b1); A read at 8M..12M */
    mma_gemm<<<dim3(DFF / 128, 2 * BLr / 128, 1), 256, MM_SMEM>>>(
        Ahi + OFF_U, Alo + OFF_U, 0, Bhi, Blo, 0, DFF, DM,
        nullptr, 0, Ahi, Alo, ffn_b1, 1);

    /* FFN2: V2 = Vh @ w2 + b2 */
    mma_gemm<<<dim3(DM / 128, 2 * BLr / 128, 1), 256, MM_SMEM>>>(
        Ahi, Alo, 0, Bhi + N_FFW, Blo + N_FFW, 0, DM, DFF,
        V2, 0, nullptr, nullptr, ffn_b2, 2);

    /* out = V2_f + V2_b + U_f + U_b */
    final_kernel<<<(BLr * DM / 4) / 256, 256>>>(V2, U, (float*)d_out);
}

// round 17
// speedup vs baseline: 1.0354x; 1.0201x over previous
#include <cuda_runtime.h>
#include <cuda_bf16.h>
#include <cstdint>

#define Bb     2
#define LL     2048
#define DM     512
#define ED_    1024
#define NS     16
#define DTR    32
#define DFF    1024
#define BLr    (Bb*LL)            /* 4096 rows */
#define NCHUNK 16
#define CLEN   (LL/NCHUNK)        /* 128 */
#define NCHAIN 2048
#define KSPL   8

typedef unsigned long long ull;

/* ------------------------------------------------------------------ */
__device__ float g_xz   [2*BLr*2*ED_];
__device__ float g_xc   [2*BLr*ED_];
__device__ float g_dbl  [2*BLr*64];
__device__ float g_part [2*KSPL*BLr*64];
__device__ float g_delta[2*BLr*ED_];
__device__ float g_U    [2*BLr*DM];
__device__ float g_V2   [2*BLr*DM];
__device__ float g_hloc [2*NCHUNK*NCHAIN*NS];
__device__ float g_aprod[2*NCHUNK*NCHAIN*NS];
__device__ float g_hin  [2*NCHUNK*NCHAIN*NS];
__device__ __nv_bfloat16 g_Ahi[12*1024*1024];
__device__ __nv_bfloat16 g_Alo[12*1024*1024];
__device__ __nv_bfloat16 g_Bhi[2*1024*1024];
__device__ __nv_bfloat16 g_Blo[2*1024*1024];

/* ------------------------------------------------------------------ */
__device__ __forceinline__ float softplusf(float x) {
    return fmaxf(x, 0.f) + log1pf(expf(-fabsf(x)));
}
__device__ __forceinline__ float siluf(float x) {
    return x / (1.f + __expf(-x));
}
__device__ __forceinline__ uint32_t smem_u32(const void* p) {
    uint32_t a;
    asm("{ .reg .u64 t; cvta.to.shared.u64 t, %1; cvt.u32.u64 %0, t; }"
        : "=r"(a) : "l"(p));
    return a;
}
__device__ __forceinline__ ull fma2(ull a, ull b, ull c) {
    ull d;
    asm("fma.rn.f32x2 %0, %1, %2, %3;" : "=l"(d) : "l"(a), "l"(b), "l"(c));
    return d;
}
__device__ __forceinline__ ull packf2(float lo, float hi) {
    ull r;
    asm("mov.b64 %0, {%1, %2};" : "=l"(r) : "f"(lo), "f"(hi));
    return r;
}
__device__ __forceinline__ float2 unpackf2(ull v) {
    float lo, hi;
    asm("mov.b64 {%0, %1}, %2;" : "=f"(lo), "=f"(hi) : "l"(v));
    return make_float2(lo, hi);
}
__device__ __forceinline__ void cp16(uint32_t dst, const void* src) {
    asm volatile("cp.async.ca.shared.global [%0], [%1], 16;"
                 :: "r"(dst), "l"(src));
}
__device__ __forceinline__ void cp_commit() {
    asm volatile("cp.async.commit_group;");
}
__device__ __forceinline__ void cp_wait0() {
    asm volatile("cp.async.wait_group 0;" ::: "memory");
}

/* ================= HMMA helpers =================================== */
__device__ __forceinline__ void ldm_x4(uint32_t* r, uint32_t addr) {
    asm volatile("ldmatrix.sync.aligned.m8n8.x4.shared.b16 {%0,%1,%2,%3}, [%4];"
                 : "=r"(r[0]), "=r"(r[1]), "=r"(r[2]), "=r"(r[3]) : "r"(addr));
}
__device__ __forceinline__ void ldm_x4t(uint32_t* r, uint32_t addr) {
    asm volatile("ldmatrix.sync.aligned.m8n8.x4.trans.shared.b16 {%0,%1,%2,%3}, [%4];"
                 : "=r"(r[0]), "=r"(r[1]), "=r"(r[2]), "=r"(r[3]) : "r"(addr));
}
__device__ __forceinline__ void mma_bf16(float* c, const uint32_t* a,
                                         const uint32_t* b) {
    asm volatile(
        "mma.sync.aligned.m16n8k16.row.col.f32.bf16.bf16.f32 "
        "{%0,%1,%2,%3},{%4,%5,%6,%7},{%8,%9},{%0,%1,%2,%3};"
        : "+f"(c[0]), "+f"(c[1]), "+f"(c[2]), "+f"(c[3])
        : "r"(a[0]), "r"(a[1]), "r"(a[2]), "r"(a[3]), "r"(b[0]), "r"(b[1]));
}

/* ================= fp32 -> bf16 hi/lo convert ===================== */
__global__ void cvt_kernel(const float* __restrict__ s,
                           __nv_bfloat16* __restrict__ hi,
                           __nv_bfloat16* __restrict__ lo, int n4)
{
    int i = blockIdx.x * 256 + threadIdx.x;
    if (i >= n4) return;
    float4 v = ((const float4*)s)[i];
    __nv_bfloat162 h01 = __floats2bfloat162_rn(v.x, v.y);
    float2 f01 = __bfloat1622float2(h01);
    __nv_bfloat162 l01 = __floats2bfloat162_rn(v.x - f01.x, v.y - f01.y);
    __nv_bfloat162 h23 = __floats2bfloat162_rn(v.z, v.w);
    float2 f23 = __bfloat1622float2(h23);
    __nv_bfloat162 l23 = __floats2bfloat162_rn(v.z - f23.x, v.w - f23.y);
    ((__nv_bfloat162*)hi)[i * 2]     = h01;
    ((__nv_bfloat162*)hi)[i * 2 + 1] = h23;
    ((__nv_bfloat162*)lo)[i * 2]     = l01;
    ((__nv_bfloat162*)lo)[i * 2 + 1] = l23;
}

__global__ void cvt2_kernel(const float* __restrict__ s0,
                            const float* __restrict__ s1,
                            __nv_bfloat16* __restrict__ hi,
                            __nv_bfloat16* __restrict__ lo,
                            size_t stride, int n4)
{
    int i = blockIdx.x * 256 + threadIdx.x;
    if (i >= n4) return;
    const float* s = blockIdx.z ? s1 : s0;
    hi += blockIdx.z * stride;
    lo += blockIdx.z * stride;
    float4 v = ((const float4*)s)[i];
    __nv_bfloat162 h01 = __floats2bfloat162_rn(v.x, v.y);
    float2 f01 = __bfloat1622float2(h01);
    __nv_bfloat162 l01 = __floats2bfloat162_rn(v.x - f01.x, v.y - f01.y);
    __nv_bfloat162 h23 = __floats2bfloat162_rn(v.z, v.w);
    float2 f23 = __bfloat1622float2(h23);
    __nv_bfloat162 l23 = __floats2bfloat162_rn(v.z - f23.x, v.w - f23.y);
    ((__nv_bfloat162*)hi)[i * 2]     = h01;
    ((__nv_bfloat162*)hi)[i * 2 + 1] = h23;
    ((__nv_bfloat162*)lo)[i * 2]     = l01;
    ((__nv_bfloat162*)lo)[i * 2 + 1] = l23;
}

/* z0: straight x cvt; z1: L-flipped x cvt */
__global__ void cvt_x2_kernel(const float* __restrict__ s,
                              __nv_bfloat16* __restrict__ hi,
                              __nv_bfloat16* __restrict__ lo, size_t stride)
{
    int i = blockIdx.x * 256 + threadIdx.x;
    hi += blockIdx.z * stride;
    lo += blockIdx.z * stride;
    float4 v;
    if (blockIdx.z == 0) {
        v = ((const float4*)s)[i];
    } else {
        int c = i & 127;
        int r = i >> 7;
        int b = r >> 11;
        int l = r & 2047;
        v = ((const float4*)s)[(size_t)(((b << 11) + (2047 - l)) << 7) + c];
    }
    __nv_bfloat162 h01 = __floats2bfloat162_rn(v.x, v.y);
    float2 f01 = __bfloat1622float2(h01);
    __nv_bfloat162 l01 = __floats2bfloat162_rn(v.x - f01.x, v.y - f01.y);
    __nv_bfloat162 h23 = __floats2bfloat162_rn(v.z, v.w);
    float2 f23 = __bfloat1622float2(h23);
    __nv_bfloat162 l23 = __floats2bfloat162_rn(v.z - f23.x, v.w - f23.y);
    ((__nv_bfloat162*)hi)[i * 2]     = h01;
    ((__nv_bfloat162*)hi)[i * 2 + 1] = h23;
    ((__nv_bfloat162*)lo)[i * 2]     = l01;
    ((__nv_bfloat162*)lo)[i * 2 + 1] = l23;
}

/* ======== split-bf16 HMMA GEMM, 2-stage cp.async, occ 2 =========== */
/* ep: 0 none, 1 bias+relu, 2 bias                                    */
#define OFF_ALO 10240
#define OFF_BHI 20480
#define OFF_BLO 29184
#define MBUF    37888
#define MM_SMEM (2*MBUF)

__global__ void __launch_bounds__(256, 2)
mma_gemm(const __nv_bfloat16* __restrict__ Ah,
         const __nv_bfloat16* __restrict__ Al, size_t sA,
         const __nv_bfloat16* __restrict__ Bh,
         const __nv_bfloat16* __restrict__ Bl, size_t sB,
         int N, int K,
         float* __restrict__ C, size_t sC,
         __nv_bfloat16* __restrict__ Chi, __nv_bfloat16* __restrict__ Clo,
         const float* __restrict__ bias, int ep)
{
    extern __shared__ char smc[];
    const int z = blockIdx.z;
    Ah += (size_t)z * sA;  Al += (size_t)z * sA;
    Bh += (size_t)z * sB;  Bl += (size_t)z * sB;
    if (C)   C   += (size_t)z * sC;
    if (Chi) { Chi += (size_t)z * sC; Clo += (size_t)z * sC; }

    const int tid  = threadIdx.x;
    const int lane = tid & 31;
    const int wid  = tid >> 5;
    const int wm   = wid & 1;
    const int wn   = wid >> 1;
    const int m0 = blockIdx.y * 128;
    const int n0 = blockIdx.x * 128;

    const int a_row = tid >> 2;
    const int a_ch  = tid & 3;
    const int b_row = tid >> 4;
    const int b_ch  = tid & 15;

    const __nv_bfloat16* gA0h = Ah + (size_t)(m0 + a_row) * K + a_ch * 8;
    const __nv_bfloat16* gA1h = gA0h + (size_t)64 * K;
    const __nv_bfloat16* gA0l = Al + (size_t)(m0 + a_row) * K + a_ch * 8;
    const __nv_bfloat16* gA1l = gA0l + (size_t)64 * K;
    const __nv_bfloat16* gB0h = Bh + (size_t)b_row * N + n0 + b_ch * 8;
    const __nv_bfloat16* gB1h = gB0h + (size_t)16 * N;
    const __nv_bfloat16* gB0l = Bl + (size_t)b_row * N + n0 + b_ch * 8;
    const __nv_bfloat16* gB1l = gB0l + (size_t)16 * N;

    const uint32_t sbase = smem_u32(smc);
    const uint32_t sa0 = (uint32_t)(a_row * 80 + a_ch * 16);
    const uint32_t sa1 = (uint32_t)((a_row + 64) * 80 + a_ch * 16);
    const uint32_t sb0 = (uint32_t)(b_row * 272 + b_ch * 16);
    const uint32_t sb1 = (uint32_t)((b_row + 16) * 272 + b_ch * 16);

    float acc[4][4][4];
#pragma unroll
    for (int i = 0; i < 4; ++i)
#pragma unroll
        for (int j = 0; j < 4; ++j)
#pragma unroll
            for (int q = 0; q < 4; ++q) acc[i][j][q] = 0.f;

    /* prolog: tile 0 via cp.async */
    {
        const uint32_t d = sbase;
        cp16(d + sa0, gA0h);            cp16(d + sa1, gA1h);
        cp16(d + OFF_ALO + sa0, gA0l);  cp16(d + OFF_ALO + sa1, gA1l);
        cp16(d + OFF_BHI + sb0, gB0h);  cp16(d + OFF_BHI + sb1, gB1h);
        cp16(d + OFF_BLO + sb0, gB0l);  cp16(d + OFF_BLO + sb1, gB1l);
        cp_commit();
        cp_wait0();
    }
    __syncthreads();

    const int NIT = K >> 5;
    for (int it = 0; it < NIT; ++it) {
        if (it + 1 < NIT) {
            const int kq = (it + 1) << 5;
            const size_t bo = (size_t)kq * N;
            const uint32_t d = sbase + (uint32_t)(((it + 1) & 1) * MBUF);
            cp16(d + sa0, gA0h + kq);            cp16(d + sa1, gA1h + kq);
            cp16(d + OFF_ALO + sa0, gA0l + kq);  cp16(d + OFF_ALO + sa1, gA1l + kq);
            cp16(d + OFF_BHI + sb0, gB0h + bo);  cp16(d + OFF_BHI + sb1, gB1h + bo);
            cp16(d + OFF_BLO + sb0, gB0l + bo);  cp16(d + OFF_BLO + sb1, gB1l + bo);
            cp_commit();
        }

        const uint32_t base = sbase + (uint32_t)((it & 1) * MBUF);
#pragma unroll
        for (int ks = 0; ks < 2; ++ks) {
            uint32_t ah[4][4], al[4][4], bh[2][4], bl[2][4];
            uint32_t aaddr = base + (uint32_t)((wm * 64 + (lane & 15)) * 80
                               + ks * 32 + ((lane >> 4) & 1) * 16);
#pragma unroll
            for (int mf = 0; mf < 4; ++mf) {
                ldm_x4(ah[mf], aaddr + mf * 1280);
                ldm_x4(al[mf], aaddr + OFF_ALO + mf * 1280);
            }
            uint32_t baddr = base + OFF_BHI
                + (uint32_t)((ks * 16 + (lane & 15)) * 272
                + (wn * 32 + ((lane >> 4) & 1) * 8) * 2);
#pragma unroll
            for (int np = 0; np < 2; ++np) {
                ldm_x4t(bh[np], baddr + np * 32);
                ldm_x4t(bl[np], baddr + (OFF_BLO - OFF_BHI) + np * 32);
            }
#pragma unroll
            for (int mf = 0; mf < 4; ++mf)
#pragma unroll
                for (int nf = 0; nf < 4; ++nf) {
                    const uint32_t* bhp = &bh[nf >> 1][(nf & 1) * 2];
                    const uint32_t* blp = &bl[nf >> 1][(nf & 1) * 2];
                    mma_bf16(acc[mf][nf], ah[mf], bhp);
                    mma_bf16(acc[mf][nf], ah[mf], blp);
                    mma_bf16(acc[mf][nf], al[mf], bhp);
                }
        }

        if (it + 1 < NIT) cp_wait0();
        __syncthreads();
    }

    /* ---- epilogue ---- */
    const int row = m0 + wm * 64 + (lane >> 2);
    const int col = n0 + wn * 32 + (lane & 3) * 2;
#pragma unroll
    for (int nf = 0; nf < 4; ++nf) {
        const int c = col + nf * 8;
        float2 bv = make_float2(0.f, 0.f);
        if (ep) bv = *(const float2*)(bias + c);
#pragma unroll
        for (int mf = 0; mf < 4; ++mf) {
            const int r = row + mf * 16;
            float2 v0 = make_float2(acc[mf][nf][0] + bv.x, acc[mf][nf][1] + bv.y);
            float2 v1 = make_float2(acc[mf][nf][2] + bv.x, acc[mf][nf][3] + bv.y);
            if (ep == 1) {
                v0.x = fmaxf(v0.x, 0.f); v0.y = fmaxf(v0.y, 0.f);
                v1.x = fmaxf(v1.x, 0.f); v1.y = fmaxf(v1.y, 0.f);
            }
            if (C) {
                *(float2*)(C + (size_t)r * N + c)       = v0;
                *(float2*)(C + (size_t)(r + 8) * N + c) = v1;
            }
            if (Chi) {
                __nv_bfloat162 h0 = __floats2bfloat162_rn(v0.x, v0.y);
                float2 f0 = __bfloat1622float2(h0);
                __nv_bfloat162 l0 = __floats2bfloat162_rn(v0.x - f0.x, v0.y - f0.y);
                __nv_bfloat162 h1 = __floats2bfloat162_rn(v1.x, v1.y);
                float2 f1 = __bfloat1622float2(h1);
                __nv_bfloat162 l1 = __floats2bfloat162_rn(v1.x - f1.x, v1.y - f1.y);
                *(__nv_bfloat162*)(Chi + (size_t)r * N + c)       = h0;
                *(__nv_bfloat162*)(Chi + (size_t)(r + 8) * N + c) = h1;
                *(__nv_bfloat162*)(Clo + (size_t)r * N + c)       = l0;
                *(__nv_bfloat162*)(Clo + (size_t)(r + 8) * N + c) = l1;
            }
        }
    }
}

/* ================= f32x2 GEMM (delta only) ========================= */
__global__ void __launch_bounds__(256, 2)
f2_gemm(const float* __restrict__ A0, const float* __restrict__ A1, int lda,
        const float* __restrict__ B0, const float* __restrict__ B1,
        int N, int K,
        float* __restrict__ C, size_t strideC,
        const float* __restrict__ bias0, const float* __restrict__ bias1,
        int ep)
{
    __shared__ float As[2][16][132];
    __shared__ float Bs[2][16][132];

    const int z = blockIdx.z;
    const float* A = z ? A1 : A0;
    const float* B = z ? B1 : B0;
    const float* bias = z ? bias1 : bias0;
    C += (size_t)z * strideC;

    const int tid = threadIdx.x;
    const int m0 = blockIdx.y * 128;
    const int n0 = blockIdx.x * 128;
    const int tm = tid >> 4;
    const int tn = tid & 15;

    const int arow = tid >> 1;
    const int acol = (tid & 1) * 8;
    const int brow = tid >> 4;
    const int bcol = (tid & 15) * 8;

    const float* gA = A + (size_t)(m0 + arow) * lda + acol;
    const float* gB = B + (size_t)brow * N + n0 + bcol;
    const uint32_t bs0 = smem_u32(&Bs[0][0][0]) + (uint32_t)((brow * 132 + bcol) * 4);
    const uint32_t bsStride = 16u * 132u * 4u;

    float4 a0, a1;

    a0 = *(const float4*)gA;  a1 = *(const float4*)(gA + 4);
    As[0][acol + 0][arow] = a0.x;  As[0][acol + 1][arow] = a0.y;
    As[0][acol + 2][arow] = a0.z;  As[0][acol + 3][arow] = a0.w;
    As[0][acol + 4][arow] = a1.x;  As[0][acol + 5][arow] = a1.y;
    As[0][acol + 6][arow] = a1.z;  As[0][acol + 7][arow] = a1.w;
    cp16(bs0,      gB);
    cp16(bs0 + 16, gB + 4);
    cp_commit();
    cp_wait0();
    __syncthreads();

    ull acc[8][4];
#pragma unroll
    for (int i = 0; i < 8; ++i)
#pragma unroll
        for (int j = 0; j < 4; ++j) acc[i][j] = 0ull;

    const int NIT = K >> 4;
    for (int it = 0; it < NIT; ++it) {
        const int buf = it & 1;
        if (it + 1 < NIT) {
            const float* pA = gA + (it + 1) * 16;
            a0 = *(const float4*)pA;  a1 = *(const float4*)(pA + 4);
            const float* pB = gB + (size_t)(it + 1) * 16 * N;
            const uint32_t d = bs0 + (buf ^ 1) * bsStride;
            cp16(d,      pB);
            cp16(d + 16, pB + 4);
            cp_commit();
        }
#pragma unroll
        for (int k = 0; k < 16; ++k) {
            float4 f0 = *(const float4*)&As[buf][k][tm * 8];
            float4 f1 = *(const float4*)&As[buf][k][tm * 8 + 4];
            ull a2[8];
            a2[0] = packf2(f0.x, f0.x);  a2[1] = packf2(f0.y, f0.y);
            a2[2] = packf2(f0.z, f0.z);  a2[3] = packf2(f0.w, f0.w);
            a2[4] = packf2(f1.x, f1.x);  a2[5] = packf2(f1.y, f1.y);
            a2[6] = packf2(f1.z, f1.z);  a2[7] = packf2(f1.w, f1.w);
            ull b2[4];
#pragma unroll
            for (int jj = 0; jj < 4; ++jj)
                b2[jj] = *(const ull*)&Bs[buf][k][tn * 2 + 32 * jj];
#pragma unroll
            for (int i = 0; i < 8; ++i)
#pragma unroll
                for (int jj = 0; jj < 4; ++jj)
                    acc[i][jj] = fma2(a2[i], b2[jj], acc[i][jj]);
        }
        if (it + 1 < NIT) {
            const int nb = buf ^ 1;
            As[nb][acol + 0][arow] = a0.x;  As[nb][acol + 1][arow] = a0.y;
            As[nb][acol + 2][arow] = a0.z;  As[nb][acol + 3][arow] = a0.w;
            As[nb][acol + 4][arow] = a1.x;  As[nb][acol + 5][arow] = a1.y;
            As[nb][acol + 6][arow] = a1.z;  As[nb][acol + 7][arow] = a1.w;
            cp_wait0();
        }
        __syncthreads();
    }

    const int crow = m0 + tm * 8;
    float2 bv[4];
#pragma unroll
    for (int jj = 0; jj < 4; ++jj) {
        if (ep) bv[jj] = *(const float2*)(bias + n0 + tn * 2 + 32 * jj);
        else    bv[jj] = make_float2(0.f, 0.f);
    }
#pragma unroll
    for (int i = 0; i < 8; ++i) {
        float* Crow = C + (size_t)(crow + i) * N + n0 + tn * 2;
#pragma unroll
        for (int jj = 0; jj < 4; ++jj) {
            float2 v = unpackf2(acc[i][jj]);
            v.x += bv[jj].x;  v.y += bv[jj].y;
            if (ep == 1) {
                v.x = fmaxf(v.x, 0.f);  v.y = fmaxf(v.y, 0.f);
            } else if (ep == 3) {
                v.x = softplusf(v.x);   v.y = softplusf(v.y);
            }
            *(float2*)(Crow + 32 * jj) = v;
        }
    }
}

/* ================= xproj split-K ==================================== */
__global__ __launch_bounds__(256)
void xproj_kernel(const float* __restrict__ xc,
                  const float* __restrict__ B0, const float* __restrict__ B1,
                  float* __restrict__ part)
{
    __shared__ float As[16][68];
    __shared__ float Bs[16][68];

    const int ks  = blockIdx.x;
    const int dir = blockIdx.z;
    const float* A = xc + (size_t)dir * BLr * ED_;
    const float* B = dir ? B1 : B0;
    float* P = part + ((size_t)dir * KSPL + ks) * BLr * 64;

    const int tid  = threadIdx.x;
    const int tx   = tid & 15;
    const int ty   = tid >> 4;
    const int row0 = blockIdx.y * 64;
    const int kbase = ks * (ED_ / KSPL);

    const int ar = tid >> 2;
    const int ak = (tid & 3) << 2;
    const int bk = tid >> 4;
    const int bn = (tid & 15) << 2;

    float acc[4][4];
#pragma unroll
    for (int i = 0; i < 4; ++i)
#pragma unroll
        for (int j = 0; j < 4; ++j) acc[i][j] = 0.f;

    for (int k0 = kbase; k0 < kbase + ED_ / KSPL; k0 += 16) {
        float4 avv = *(const float4*)(A + (size_t)(row0 + ar) * ED_ + k0 + ak);
        As[ak + 0][ar] = avv.x;
        As[ak + 1][ar] = avv.y;
        As[ak + 2][ar] = avv.z;
        As[ak + 3][ar] = avv.w;
        *(float4*)&Bs[bk][bn] =
            *(const float4*)(B + (size_t)(k0 + bk) * 64 + bn);
        __syncthreads();

#pragma unroll
        for (int kk = 0; kk < 16; ++kk) {
            float4 a = *(const float4*)&As[kk][ty << 2];
            float4 b = *(const float4*)&Bs[kk][tx << 2];
            float ai[4] = {a.x, a.y, a.z, a.w};
            float bj[4] = {b.x, b.y, b.z, b.w};
#pragma unroll
            for (int i = 0; i < 4; ++i)
#pragma unroll
                for (int j = 0; j < 4; ++j)
                    acc[i][j] = fmaf(ai[i], bj[j], acc[i][j]);
        }
        __syncthreads();
    }

    const int m0 = row0 + (ty << 2);
    const int n0 = tx << 2;
#pragma unroll
    for (int i = 0; i < 4; ++i)
        *(float4*)(P + (size_t)(m0 + i) * 64 + n0) =
            make_float4(acc[i][0], acc[i][1], acc[i][2], acc[i][3]);
}

__global__ void xproj_reduce(const float* __restrict__ part,
                             float* __restrict__ dbl)
{
    const int idx = blockIdx.x * 256 + threadIdx.x;
    const int dir = idx >> 16;
    const int r   = idx & 65535;
    const float4* p = (const float4*)part + (size_t)dir * KSPL * 65536 + r;
    float4 s = make_float4(0.f, 0.f, 0.f, 0.f);
#pragma unroll
    for (int ks = 0; ks < KSPL; ++ks) {
        float4 v = p[(size_t)ks * 65536];
        s.x += v.x; s.y += v.y; s.z += v.z; s.w += v.w;
    }
    ((float4*)dbl)[idx] = s;
}

/* ------------------------------------------------------------------ */
/* depthwise causal conv (K=4) + bias + silu: sliding-window form.     */
/* Each thread: one channel e, 4 consecutive l. 7 coalesced loads,     */
/* 16 FMA, 4 outputs.                                                  */
__global__ void conv_silu_kernel(const float* __restrict__ xz,
                                 const float* __restrict__ cw0,
                                 const float* __restrict__ cb0,
                                 const float* __restrict__ cw1,
                                 const float* __restrict__ cb1,
                                 float* __restrict__ xc)
{
    const int dir = blockIdx.z;
    const float* cw = dir ? cw1 : cw0;
    const float* cb = dir ? cb1 : cb0;
    xz += (size_t)dir * BLr * 2 * ED_;
    xc += (size_t)dir * BLr * ED_;

    int idx = blockIdx.x * 256 + threadIdx.x;   /* < BLr/4 * ED_ */
    int e  = idx & 1023;
    int rq = idx >> 10;                         /* 0..BLr/4-1 */
    int row0 = rq << 2;                         /* first of 4 rows */
    int l0 = row0 & 2047;                       /* within batch */

    const float4 w4 = *(const float4*)&cw[e << 2];
    const float bias = cb[e];

    /* window w[0..6] = xz[row0-3 .. row0+3][e] (zeros before batch start) */
    float w[7];
#pragma unroll
    for (int k = 0; k < 3; ++k) {
        int lw = l0 - 3 + k;
        w[k] = (lw >= 0)
             ? xz[((size_t)(row0 - 3 + k) << 11) + e] : 0.f;
    }
#pragma unroll
    for (int k = 3; k < 7; ++k)
        w[k] = xz[((size_t)(row0 - 3 + k) << 11) + e];

#pragma unroll
    for (int s = 0; s < 4; ++s) {
        float acc = bias;
        acc = fmaf(w[s + 0], w4.x, acc);
        acc = fmaf(w[s + 1], w4.y, acc);
        acc = fmaf(w[s + 2], w4.z, acc);
        acc = fmaf(w[s + 3], w4.w, acc);
        xc[((size_t)(row0 + s) << 10) + e] = siluf(acc);
    }
}

/* ================= chunked selective scan (4 states/lane) ========== */
__global__ __launch_bounds__(256)
void scanA_kernel(const float* __restrict__ delta,
                  const float* __restrict__ xc,
                  const float* __restrict__ dbl,
                  const float* __restrict__ Alog0,
                  const float* __restrict__ Alog1,
                  float* __restrict__ hloc, float* __restrict__ aprod)
{
    const int dir  = blockIdx.y;
    const int warp = blockIdx.x * 8 + (threadIdx.x >> 5);
    const int lane = threadIdx.x & 31;
    const int c    = lane >> 2;
    const int g    = lane & 3;
    const int chunk = warp >> 8;
    const int cg    = warp & 255;
    const int chain = cg * 8 + c;
    const int b = chain >> 10;
    const int e = chain & 1023;

    const float* Alog = dir ? Alog1 : Alog0;
    delta += (size_t)dir * BLr * ED_;
    xc    += (size_t)dir * BLr * ED_;
    dbl   += (size_t)dir * BLr * 64;

    float4 alv = *(const float4*)&Alog[(e << 4) + g * 4];
    const float a0 = -expf(alv.x), a1 = -expf(alv.y),
                a2 = -expf(alv.z), a3 = -expf(alv.w);
    float h0 = 0.f, h1 = 0.f, h2 = 0.f, h3 = 0.f;
    float p0 = 1.f, p1 = 1.f, p2 = 1.f, p3 = 1.f;
    const int r0 = (b << 11) + chunk * CLEN;

    for (int l = 0; l < CLEN; l += 4) {
        float d[4], xv[4];
        float4 bv[4];
#pragma unroll
        for (int s = 0; s < 4; ++s) {
            int row = r0 + l + s;
            d[s]  = __ldg(&delta[((size_t)row << 10) + e]);
            xv[s] = __ldg(&xc   [((size_t)row << 10) + e]);
            bv[s] = *(const float4*)&dbl[(row << 6) + 32 + g * 4];
        }
#pragma unroll
        for (int s = 0; s < 4; ++s) {
            const float t = d[s] * xv[s];
            float dA;
            dA = __expf(d[s] * a0); h0 = fmaf(dA, h0, t * bv[s].x); p0 *= dA;
            dA = __expf(d[s] * a1); h1 = fmaf(dA, h1, t * bv[s].y); p1 *= dA;
            dA = __expf(d[s] * a2); h2 = fmaf(dA, h2, t * bv[s].z); p2 *= dA;
            dA = __expf(d[s] * a3); h3 = fmaf(dA, h3, t * bv[s].w); p3 *= dA;
        }
    }
    size_t idx = ((size_t)dir * NCHUNK + chunk) * (NCHAIN * NS)
               + (size_t)chain * NS + g * 4;
    *(float4*)&hloc[idx]  = make_float4(h0, h1, h2, h3);
    *(float4*)&aprod[idx] = make_float4(p0, p1, p2, p3);
}

__global__ void scanB_kernel(const float* __restrict__ hloc,
                             const float* __restrict__ aprod,
                             float* __restrict__ hin)
{
    const int dir = blockIdx.y;
    const int t = blockIdx.x * 256 + threadIdx.x;
    const size_t base = (size_t)dir * NCHUNK * NCHAIN * NS;
    float h = 0.f;
#pragma unroll
    for (int c = 0; c < NCHUNK; ++c) {
        size_t idx = base + (size_t)c * NCHAIN * NS + t;
        hin[idx] = h;
        h = fmaf(aprod[idx], h, hloc[idx]);
    }
}

__global__ __launch_bounds__(256)
void scanC_kernel(const float* __restrict__ delta,
                  const float* __restrict__ xc,
                  const float* __restrict__ dbl,
                  const float* __restrict__ xz,
                  const float* __restrict__ Alog0,
                  const float* __restrict__ Alog1,
                  const float* __restrict__ Dp0,
                  const float* __restrict__ Dp1,
                  const float* __restrict__ hin,
                  __nv_bfloat16* __restrict__ yhi,
                  __nv_bfloat16* __restrict__ ylo)
{
    const int dir  = blockIdx.y;
    const int warp = blockIdx.x * 8 + (threadIdx.x >> 5);
    const int lane = threadIdx.x & 31;
    const int c    = lane >> 2;
    const int g    = lane & 3;
    const int chunk = warp >> 8;
    const int cg    = warp & 255;
    const int chain = cg * 8 + c;
    const int b = chain >> 10;
    const int e = chain & 1023;

    const float* Alog = dir ? Alog1 : Alog0;
    const float* Dp   = dir ? Dp1   : Dp0;
    delta += (size_t)dir * BLr * ED_;
    xc    += (size_t)dir * BLr * ED_;
    yhi   += (size_t)dir * BLr * ED_;
    ylo   += (size_t)dir * BLr * ED_;
    dbl   += (size_t)dir * BLr * 64;
    xz    += (size_t)dir * BLr * 2 * ED_;

    float4 alv = *(const float4*)&Alog[(e << 4) + g * 4];
    const float a0 = -expf(alv.x), a1 = -expf(alv.y),
                a2 = -expf(alv.z), a3 = -expf(alv.w);
    const float dc = Dp[e];
    float4 hv = *(const float4*)&hin[((size_t)dir * NCHUNK + chunk)
               * (NCHAIN * NS) + (size_t)chain * NS + g * 4];
    float h0 = hv.x, h1 = hv.y, h2 = hv.z, h3 = hv.w;
    const int r0 = (b << 11) + chunk * CLEN;

    for (int l = 0; l < CLEN; l += 4) {
        float d[4], xv[4];
        float4 bv[4], cv[4];
#pragma unroll
        for (int s = 0; s < 4; ++s) {
            int row = r0 + l + s;
            d[s]  = __ldg(&delta[((size_t)row << 10) + e]);
            xv[s] = __ldg(&xc   [((size_t)row << 10) + e]);
            bv[s] = *(const float4*)&dbl[(row << 6) + 32 + g * 4];
            cv[s] = *(const float4*)&dbl[(row << 6) + 48 + g * 4];
        }
        float p[4];
#pragma unroll
        for (int s = 0; s < 4; ++s) {
            const float t = d[s] * xv[s];
            float dA;
            dA = __expf(d[s] * a0); h0 = fmaf(dA, h0, t * bv[s].x);
            dA = __expf(d[s] * a1); h1 = fmaf(dA, h1, t * bv[s].y);
            dA = __expf(d[s] * a2); h2 = fmaf(dA, h2, t * bv[s].z);
            dA = __expf(d[s] * a3); h3 = fmaf(dA, h3, t * bv[s].w);
            p[s] = h0 * cv[s].x + h1 * cv[s].y + h2 * cv[s].z + h3 * cv[s].w;
        }
#pragma unroll
        for (int s = 0; s < 4; ++s) {
            p[s] += __shfl_xor_sync(0xffffffffu, p[s], 1);
            p[s] += __shfl_xor_sync(0xffffffffu, p[s], 2);
        }
        if (g == 0) {
#pragma unroll
            for (int s = 0; s < 4; ++s) {
                int row = r0 + l + s;
                float zv = xz[((size_t)row << 11) + 1024 + e];
                float val = (p[s] + xv[s] * dc) * siluf(zv);
                __nv_bfloat16 hb = __float2bfloat16_rn(val);
                yhi[((size_t)row << 10) + e] = hb;
                ylo[((size_t)row << 10) + e] =
                    __float2bfloat16_rn(val - __bfloat162float(hb));
            }
        }
    }
}

/* ---- layernorm; also emits bf16 hi/lo of the result -------------- */
__global__ __launch_bounds__(128)
void ln_kernel(float* __restrict__ U, const float* __restrict__ g,
               const float* __restrict__ bb,
               __nv_bfloat16* __restrict__ hi, __nv_bfloat16* __restrict__ lo)
{
    int row = blockIdx.x;
    float4* p = (float4*)(U + (size_t)row * DM);
    int tid = threadIdx.x;
    int lane = tid & 31, w = tid >> 5;
    __shared__ float red[4];

    float4 v = p[tid];
    float s = v.x + v.y + v.z + v.w;
#pragma unroll
    for (int o = 16; o; o >>= 1) s += __shfl_xor_sync(0xffffffffu, s, o);
    if (!lane) red[w] = s;
    __syncthreads();
    float mu = (red[0] + red[1] + red[2] + red[3]) * (1.f / 512.f);

    float dx = v.x - mu, dy = v.y - mu, dz = v.z - mu, dw = v.w - mu;
    float s2 = dx*dx + dy*dy + dz*dz + dw*dw;
#pragma unroll
    for (int o = 16; o; o >>= 1) s2 += __shfl_xor_sync(0xffffffffu, s2, o);
    __syncthreads();
    if (!lane) red[w] = s2;
    __syncthreads();
    float var  = (red[0] + red[1] + red[2] + red[3]) * (1.f / 512.f);
    float rstd = rsqrtf(var + 1e-5f);

    int c = tid << 2;
    float4 go = *(const float4*)(g + c);
    float4 bo = *(const float4*)(bb + c);
    float4 o;
    o.x = dx * rstd * go.x + bo.x;
    o.y = dy * rstd * go.y + bo.y;
    o.z = dz * rstd * go.z + bo.z;
    o.w = dw * rstd * go.w + bo.w;
    p[tid] = o;

    __nv_bfloat162 h01 = __floats2bfloat162_rn(o.x, o.y);
    float2 f01 = __bfloat1622float2(h01);
    __nv_bfloat162 l01 = __floats2bfloat162_rn(o.x - f01.x, o.y - f01.y);
    __nv_bfloat162 h23 = __floats2bfloat162_rn(o.z, o.w);
    float2 f23 = __bfloat1622float2(h23);
    __nv_bfloat162 l23 = __floats2bfloat162_rn(o.z - f23.x, o.w - f23.y);
    size_t base = (size_t)row * DM + c;
    *(__nv_bfloat162*)(hi + base)     = h01;
    *(__nv_bfloat162*)(hi + base + 2) = h23;
    *(__nv_bfloat162*)(lo + base)     = l01;
    *(__nv_bfloat162*)(lo + base + 2) = l23;
}

/* ------------------------------------------------------------------ */
__global__ void final_kernel(const float* __restrict__ V2,
                             const float* __restrict__ U,
                             float* __restrict__ out)
{
    int idx = blockIdx.x * 256 + threadIdx.x;
    const int off = (BLr * DM) >> 2;
    float4 a = ((const float4*)V2)[idx];
    float4 b = ((const float4*)V2)[idx + off];
    float4 c = ((const float4*)U)[idx];
    float4 d = ((const float4*)U)[idx + off];
    float4 o;
    o.x = a.x + b.x + c.x + d.x;
    o.y = a.y + b.y + c.y + d.y;
    o.z = a.z + b.z + c.z + d.z;
    o.w = a.w + b.w + c.w + d.w;
    ((float4*)out)[idx] = o;
}

/* ------------------------------------------------------------------ */
extern "C" void kernel_launch(void* const* d_in, const int* in_sizes, int n_in,
                              void* d_out, int out_size)
{
    (void)in_sizes; (void)n_in; (void)out_size;

    float *xz, *xc, *dbl, *part, *delta, *U, *V2, *hloc, *aprod, *hin;
    __nv_bfloat16 *Ahi, *Alo, *Bhi, *Blo;
    cudaGetSymbolAddress((void**)&xz,    g_xz);
    cudaGetSymbolAddress((void**)&xc,    g_xc);
    cudaGetSymbolAddress((void**)&dbl,   g_dbl);
    cudaGetSymbolAddress((void**)&part,  g_part);
    cudaGetSymbolAddress((void**)&delta, g_delta);
    cudaGetSymbolAddress((void**)&U,     g_U);
    cudaGetSymbolAddress((void**)&V2,    g_V2);
    cudaGetSymbolAddress((void**)&hloc,  g_hloc);
    cudaGetSymbolAddress((void**)&aprod, g_aprod);
    cudaGetSymbolAddress((void**)&hin,   g_hin);
    cudaGetSymbolAddress((void**)&Ahi,   g_Ahi);
    cudaGetSymbolAddress((void**)&Alo,   g_Alo);
    cudaGetSymbolAddress((void**)&Bhi,   g_Bhi);
    cudaGetSymbolAddress((void**)&Blo,   g_Blo);

    cudaFuncSetAttribute(mma_gemm, cudaFuncAttributeMaxDynamicSharedMemorySize,
                         MM_SMEM);

    const float* x = (const float*)d_in[0];
    const float* norm1_g = (const float*)d_in[19];
    const float* norm1_b = (const float*)d_in[20];
    const float* ffn_w1  = (const float*)d_in[23];
    const float* ffn_b1  = (const float*)d_in[24];
    const float* ffn_w2  = (const float*)d_in[25];
    const float* ffn_b2  = (const float*)d_in[26];

    const float* W[2][9];
    for (int dir = 0; dir < 2; ++dir)
        for (int k = 0; k < 9; ++k)
            W[dir][k] = (const float*)d_in[1 + dir * 9 + k];

    const size_t N_X   = (size_t)BLr * DM;        /* 2M  */
    const size_t N_Y   = (size_t)BLr * ED_;       /* 4M  */
    const size_t N_INW = (size_t)DM * 2 * ED_;    /* 1M  */
    const size_t N_OUW = (size_t)ED_ * DM;        /* 512K */
    const size_t N_FFW = (size_t)DM * DFF;        /* 512K */
    const size_t OFF_U = 4 * N_X;                 /* U bf16 staging at 8M */

    /* stage GEMM1 operands: x straight+flipped (one launch), weights */
    cvt_x2_kernel<<<dim3((int)(N_X / 4 / 256), 1, 2), 256>>>(x, Ahi, Alo, N_X);
    cvt2_kernel<<<dim3((int)(N_INW / 4 / 256), 1, 2), 256>>>(
        W[0][0], W[1][0], Bhi, Blo, N_INW, (int)(N_INW / 4));

    /* GEMM1: xz = [x|xb] @ in_w : 4096x2048x512, z=2 */
    mma_gemm<<<dim3(2 * ED_ / 128, BLr / 128, 2), 256, MM_SMEM>>>(
        Ahi, Alo, N_X, Bhi, Blo, N_INW, 2 * ED_, DM,
        xz, (size_t)BLr * 2 * ED_, nullptr, nullptr, nullptr, 0);

    /* conv + silu (sliding window: 4 l per thread) */
    conv_silu_kernel<<<dim3((BLr / 4 * ED_) / 256, 1, 2), 256>>>(
        xz, W[0][1], W[0][2], W[1][1], W[1][2], xc);

    /* xproj split-K + reduce */
    xproj_kernel<<<dim3(KSPL, BLr / 64, 2), 256>>>(xc, W[0][3], W[1][3], part);
    xproj_reduce<<<(2 * BLr * 64 / 4) / 256, 256>>>(part, dbl);

    /* delta = softplus(dt @ dt_w + dt_b) : f32x2 path (K=32) */
    f2_gemm<<<dim3(ED_ / 128, BLr / 128, 2), 256>>>(
        dbl, dbl + (size_t)BLr * 64, 64, W[0][4], W[1][4], ED_, DTR,
        delta, (size_t)BLr * ED_, W[0][5], W[1][5], 3);

    /* chunked scan (4 states/lane); scanC writes y bf16 hi/lo at 0 */
    scanA_kernel<<<dim3(512, 2), 256>>>(
        delta, xc, dbl, W[0][6], W[1][6], hloc, aprod);
    scanB_kernel<<<dim3(128, 2), 256>>>(hloc, aprod, hin);
    scanC_kernel<<<dim3(512, 2), 256>>>(
        delta, xc, dbl, xz, W[0][6], W[1][6], W[0][7], W[1][7], hin, Ahi, Alo);

    /* GEMM4: U = y @ out_w (fp32) + U bf16 hi/lo staged at OFF_U */
    cvt2_kernel<<<dim3((int)(N_OUW / 4 / 256), 1, 2), 256>>>(
        W[0][8], W[1][8], Bhi, Blo, N_OUW, (int)(N_OUW / 4));
    mma_gemm<<<dim3(DM / 128, BLr / 128, 2), 256, MM_SMEM>>>(
        Ahi, Alo, N_Y, Bhi, Blo, N_OUW, DM, ED_,
        U, N_X, Ahi + OFF_U, Alo + OFF_U, nullptr, 0);

    /* layernorm on forward branch (re-stages its bf16 hi/lo) */
    ln_kernel<<<BLr, 128>>>(U, norm1_g, norm1_b, Ahi + OFF_U, Alo + OFF_U);

    /* stage both FFN weights */
    cvt2_kernel<<<dim3((int)(N_FFW / 4 / 256), 1, 2), 256>>>(
        ffn_w1, ffn_w2, Bhi, Blo, N_FFW, (int)(N_FFW / 4));

    /* FFN1: Vh(hi/lo at 0..8M) = relu(U @ w1 + b1); A read at 8M..12M */
    mma_gemm<<<dim3(DFF / 128, 2 * BLr / 128, 1), 256, MM_SMEM>>>(
        Ahi + OFF_U, Alo + OFF_U, 0, Bhi, Blo, 0, DFF, DM,
        nullptr, 0, Ahi, Alo, ffn_b1, 1);

    /* FFN2: V2 = Vh @ w2 + b2 */
    mma_gemm<<<dim3(DM / 128, 2 * BLr / 128, 1), 256, MM_SMEM>>>(
        Ahi, Alo, 0, Bhi + N_FFW, Blo + N_FFW, 0, DM, DFF,
        V2, 0, nullptr, nullptr, ffn_b2, 2);

    /* out = V2_f + V2_b + U_f + U_b */
    final_kernel<<<(BLr * DM / 4) / 256, 256>>>(V2, U, (float*)d_out);
}